// round 6
// baseline (speedup 1.0000x reference)
#include <cuda_runtime.h>
#include <math.h>

// Problem constants
#define BB 2
#define NN 1024
#define CSD 384
#define HH 12
#define CC 16
#define PQN 4
#define PVN 8
#define NPAD 1026        // N + 2*PAD
#define PROW 512         // num_pool
#define TT 1538          // NPAD + PROW
#define HC 192           // H*C
#define HPQ3 144         // H*PQ*3
#define HPV3 288         // H*PV*3
#define OCW 576          // HC + HPV3 + H*PV
#define ATTS 8           // split-KV factor
#define ACHUNK ((TT + ATTS - 1) / ATTS)   // 193

#define C1 0.176776695f       // w_l * (1/sqrt(C))
#define WC_HALF 0.117851130f  // w_c/2

// Scratch (device globals)
__device__ float g_s_pool[BB*PROW*CSD];
__device__ float g_t_all[BB*TT*3];
__device__ float g_r_all[BB*TT*9];
__device__ float g_k0 [BB*NN*HC];
__device__ float g_v0 [BB*NN*HC];
__device__ float g_kp0[BB*NN*HPQ3];
__device__ float g_vp0[BB*NN*HPV3];
__device__ float g_k  [BB*TT*HC];
__device__ float g_v  [BB*TT*HC];
__device__ float g_kp [BB*TT*HPQ3];
__device__ float g_vp [BB*TT*HPV3];
__device__ float g_sk [BB*TT*HH];
__device__ float g_q  [BB*PROW*HC];
__device__ float g_qp [BB*PROW*HPQ3];
__device__ float g_oc [BB*PROW*OCW];
__device__ float g_wfold[6*OCW];

#define NPART (BB*PROW*HH*ATTS)
__device__ float g_pm[NPART];
__device__ float g_pl[NPART];
__device__ float g_po[NPART*CC];
__device__ float g_pg[NPART*PVN*3];

__device__ __forceinline__ int clampsrc(int e) {
    int v = e - 1;
    return v < 0 ? 0 : (v > NN - 1 ? NN - 1 : v);
}

// ---------------------------------------------------------------------------
// Prep: pooled s rows + t_all / r_all
// ---------------------------------------------------------------------------
#define SP_TOT (BB*PROW*CSD)
#define TR_TOT (BB*TT*12)
__global__ void prep_all_kernel(const float* __restrict__ s,
                                const float* __restrict__ trans,
                                const float* __restrict__ rots) {
    int idx = blockIdx.x * blockDim.x + threadIdx.x;
    if (idx < SP_TOT) {
        int c = idx % CSD;
        int bp = idx / CSD;
        int p = bp % PROW;
        int b = bp / PROW;
        g_s_pool[idx] = (s[(b * NN + clampsrc(2 * p    )) * CSD + c]
                       + s[(b * NN + clampsrc(2 * p + 1)) * CSD + c]
                       + s[(b * NN + clampsrc(2 * p + 2)) * CSD + c]) * (1.f / 3.f);
        return;
    }
    int k = idx - SP_TOT;
    if (k >= TR_TOT) return;
    int d = k % 12;
    int bt = k / 12;
    int t = bt % TT;
    int b = bt / TT;
    if (d < 3) {
        float val;
        if (t < NPAD) {
            val = trans[(b * NN + clampsrc(t)) * 3 + d];
        } else {
            int p = t - NPAD;
            val = (trans[(b * NN + clampsrc(2 * p    )) * 3 + d]
                 + trans[(b * NN + clampsrc(2 * p + 1)) * 3 + d]
                 + trans[(b * NN + clampsrc(2 * p + 2)) * 3 + d]) * (1.f / 3.f);
        }
        g_t_all[(b * TT + t) * 3 + d] = val;
    } else {
        int r = d - 3;
        float val;
        if (t < NPAD) {
            val = rots[(b * NN + clampsrc(t)) * 9 + r];
        } else {
            int p = t - NPAD;
            val = (rots[(b * NN + clampsrc(2 * p    )) * 9 + r]
                 + rots[(b * NN + clampsrc(2 * p + 1)) * 9 + r]
                 + rots[(b * NN + clampsrc(2 * p + 2)) * 9 + r]) * (1.f / 3.f);
        }
        g_r_all[(b * TT + t) * 9 + r] = val;
    }
}

// ---------------------------------------------------------------------------
// Fused multi-task SGEMM: tile 64x64, BK=16, 256 threads, 4x4/thread.
// Double-buffered smem: one __syncthreads per K-step.
// ---------------------------------------------------------------------------
#define NTASK 6
struct GemmTask {
    const float* A;
    const float* B;
    float* C;
    int M, N, K, gx;
};
struct TaskPack {
    GemmTask t[NTASK];
    int ofs[NTASK + 1];
};

#define GBM 64
#define GBN 64
#define GBK 16
__global__ void mgemm_kernel(TaskPack P) {
    int bid = blockIdx.x;
    int ti = 0;
#pragma unroll
    for (int x = 0; x < NTASK - 1; x++)
        if (bid >= P.ofs[x + 1]) ti = x + 1;
    GemmTask tk = P.t[ti];
    int lb = bid - P.ofs[ti];
    int bx = lb % tk.gx, by = lb / tk.gx;

    __shared__ float As[2][GBK][GBM];
    __shared__ float Bs[2][GBK][GBN];
    int tid = threadIdx.x;
    int tx = tid % 16, ty = tid / 16;
    int row0 = by * GBM;
    int col0 = bx * GBN;
    const float* A = tk.A;
    const float* Bm = tk.B;
    int M = tk.M, Nn = tk.N, K = tk.K;

    // per-thread load coords (4 A elems + 4 B elems per K-step)
    // A: li = tid + x*256 -> m = li/16, kk = li%16
    // B: kk = li/64, n = li%64
    float acc[4][4];
#pragma unroll
    for (int i = 0; i < 4; i++)
#pragma unroll
        for (int j = 0; j < 4; j++) acc[i][j] = 0.f;

    float ra[4], rb[4];
    // prefetch tile 0 into regs
    {
        int k0 = 0;
#pragma unroll
        for (int x = 0; x < 4; x++) {
            int li = tid + x * 256;
            int m = li / GBK, kk = li % GBK;
            int gm = row0 + m;
            ra[x] = (gm < M) ? A[(long)gm * K + k0 + kk] : 0.f;
        }
#pragma unroll
        for (int x = 0; x < 4; x++) {
            int li = tid + x * 256;
            int kk = li / GBN, n = li % GBN;
            int gn = col0 + n;
            rb[x] = (gn < Nn) ? Bm[(long)(k0 + kk) * Nn + gn] : 0.f;
        }
    }
    // store tile 0
#pragma unroll
    for (int x = 0; x < 4; x++) {
        int li = tid + x * 256;
        As[0][li % GBK][li / GBK] = ra[x];
        Bs[0][li / GBN][li % GBN] = rb[x];
    }
    __syncthreads();

    int nsteps = K / GBK;
    int cur = 0;
    for (int step = 0; step < nsteps; step++) {
        // prefetch next tile into regs (overlaps with compute)
        if (step + 1 < nsteps) {
            int k0 = (step + 1) * GBK;
#pragma unroll
            for (int x = 0; x < 4; x++) {
                int li = tid + x * 256;
                int m = li / GBK, kk = li % GBK;
                int gm = row0 + m;
                ra[x] = (gm < M) ? A[(long)gm * K + k0 + kk] : 0.f;
            }
#pragma unroll
            for (int x = 0; x < 4; x++) {
                int li = tid + x * 256;
                int kk = li / GBN, n = li % GBN;
                int gn = col0 + n;
                rb[x] = (gn < Nn) ? Bm[(long)(k0 + kk) * Nn + gn] : 0.f;
            }
        }
        // compute on current buffer
#pragma unroll
        for (int kk = 0; kk < GBK; kk++) {
            float a[4], bvals[4];
#pragma unroll
            for (int i = 0; i < 4; i++) a[i] = As[cur][kk][ty * 4 + i];
#pragma unroll
            for (int j = 0; j < 4; j++) bvals[j] = Bs[cur][kk][tx * 4 + j];
#pragma unroll
            for (int i = 0; i < 4; i++)
#pragma unroll
                for (int j = 0; j < 4; j++) acc[i][j] += a[i] * bvals[j];
        }
        // store next tile into alternate buffer
        if (step + 1 < nsteps) {
            int nxt = cur ^ 1;
#pragma unroll
            for (int x = 0; x < 4; x++) {
                int li = tid + x * 256;
                As[nxt][li % GBK][li / GBK] = ra[x];
                Bs[nxt][li / GBN][li % GBN] = rb[x];
            }
            __syncthreads();
            cur = nxt;
        }
    }
#pragma unroll
    for (int i = 0; i < 4; i++) {
        int gm = row0 + ty * 4 + i;
        if (gm >= M) continue;
#pragma unroll
        for (int j = 0; j < 4; j++) {
            int gn = col0 + tx * 4 + j;
            if (gn < Nn) tk.C[(long)gm * Nn + gn] = acc[i][j];
        }
    }
}

// ---------------------------------------------------------------------------
// Weight fold: warp per OCW-row.
// ---------------------------------------------------------------------------
__global__ void fold_w_kernel(const float* __restrict__ wout,
                              const float* __restrict__ wupd) {
    int gw = (blockIdx.x * blockDim.x + threadIdx.x) >> 5;
    int lane = threadIdx.x & 31;
    if (gw >= OCW) return;
    const float* wr = wout + (long)gw * CSD;
    float acc[6] = {0, 0, 0, 0, 0, 0};
    for (int m = lane; m < CSD; m += 32) {
        float w = wr[m];
#pragma unroll
        for (int j = 0; j < 6; j++) acc[j] += w * __ldg(&wupd[m * 6 + j]);
    }
#pragma unroll
    for (int off = 16; off > 0; off >>= 1)
#pragma unroll
        for (int j = 0; j < 6; j++)
            acc[j] += __shfl_down_sync(0xffffffffu, acc[j], off);
    if (lane == 0) {
#pragma unroll
        for (int j = 0; j < 6; j++) g_wfold[j * OCW + gw] = acc[j];
    }
}

// ---------------------------------------------------------------------------
// Expand + transform, restructured:
//  range A: k/v copy-or-average, one thread per float4 chunk (high MLP)
//  range B: kp/vp expand+rotate+sk per (b,t,h)
//  range C: q point rotate per (b,i,h)
// ---------------------------------------------------------------------------
#define KVCH (BB*TT*(HC/4)*2)      // k and v float4 chunks
#define KV_TOT (BB*TT*HH)
#define Q_TOT (BB*PROW*HH)
__device__ __forceinline__ float4 avg3f4(float4 a, float4 b, float4 c) {
    return make_float4((a.x + b.x + c.x) * (1.f / 3.f),
                       (a.y + b.y + c.y) * (1.f / 3.f),
                       (a.z + b.z + c.z) * (1.f / 3.f),
                       (a.w + b.w + c.w) * (1.f / 3.f));
}
__global__ void expand_transform_kernel() {
    int idx = blockIdx.x * blockDim.x + threadIdx.x;
    if (idx < KVCH) {
        int c = idx % (HC / 4);          // float4 chunk within row
        int rest = idx / (HC / 4);
        int rt = rest % (BB * TT);       // b*TT + t
        int sel = rest / (BB * TT);      // 0 = k, 1 = v
        int t = rt % TT;
        int b = rt / TT;
        const float* srcbase = sel ? g_v0 : g_k0;
        float* dstbase = sel ? g_v : g_k;
        float4 val;
        if (t < NPAD) {
            int r0 = clampsrc(t);
            val = reinterpret_cast<const float4*>(srcbase + ((long)(b * NN + r0) * HC))[c];
        } else {
            int p = t - NPAD;
            int r0 = clampsrc(2 * p), r1 = clampsrc(2 * p + 1), r2 = clampsrc(2 * p + 2);
            float4 a = reinterpret_cast<const float4*>(srcbase + ((long)(b * NN + r0) * HC))[c];
            float4 bb = reinterpret_cast<const float4*>(srcbase + ((long)(b * NN + r1) * HC))[c];
            float4 cc = reinterpret_cast<const float4*>(srcbase + ((long)(b * NN + r2) * HC))[c];
            val = avg3f4(a, bb, cc);
        }
        reinterpret_cast<float4*>(dstbase + ((long)rt * HC))[c] = val;
        return;
    }
    int idx2 = idx - KVCH;
    if (idx2 < KV_TOT) {
        int h = idx2 % HH;
        int rt = idx2 / HH;
        int t = rt % TT;
        int b = rt / TT;

        int r0, r1 = 0, r2 = 0;
        bool pool;
        if (t < NPAD) {
            r0 = clampsrc(t);
            pool = false;
        } else {
            int p = t - NPAD;
            r0 = clampsrc(2 * p);
            r1 = clampsrc(2 * p + 1);
            r2 = clampsrc(2 * p + 2);
            pool = true;
        }

        float R[9], tr[3];
#pragma unroll
        for (int r = 0; r < 9; r++) R[r] = g_r_all[rt * 9 + r];
#pragma unroll
        for (int r = 0; r < 3; r++) tr[r] = g_t_all[rt * 3 + r];

        // kp
        {
            float lp[PQN * 3];
            const float4* a = reinterpret_cast<const float4*>(g_kp0 + ((long)(b * NN + r0) * HPQ3 + h * PQN * 3));
            const float4* bb = reinterpret_cast<const float4*>(g_kp0 + ((long)(b * NN + r1) * HPQ3 + h * PQN * 3));
            const float4* cc = reinterpret_cast<const float4*>(g_kp0 + ((long)(b * NN + r2) * HPQ3 + h * PQN * 3));
#pragma unroll
            for (int c = 0; c < 3; c++) {
                float4 v = pool ? avg3f4(a[c], bb[c], cc[c]) : a[c];
                lp[c*4+0] = v.x; lp[c*4+1] = v.y; lp[c*4+2] = v.z; lp[c*4+3] = v.w;
            }
            float sk = 0.f;
            float gp[PQN * 3];
#pragma unroll
            for (int p = 0; p < PQN; p++) {
                float lx = lp[p*3+0], ly = lp[p*3+1], lz = lp[p*3+2];
                float gx = R[0]*lx + R[1]*ly + R[2]*lz + tr[0];
                float gy = R[3]*lx + R[4]*ly + R[5]*lz + tr[1];
                float gz = R[6]*lx + R[7]*ly + R[8]*lz + tr[2];
                gp[p*3+0] = gx; gp[p*3+1] = gy; gp[p*3+2] = gz;
                sk += gx*gx + gy*gy + gz*gz;
            }
            g_sk[rt * HH + h] = sk;
            float4* dst = reinterpret_cast<float4*>(g_kp + ((long)rt * HPQ3 + h * PQN * 3));
#pragma unroll
            for (int c = 0; c < 3; c++)
                dst[c] = make_float4(gp[c*4+0], gp[c*4+1], gp[c*4+2], gp[c*4+3]);
        }
        // vp
        {
            float lp[PVN * 3];
            const float4* a = reinterpret_cast<const float4*>(g_vp0 + ((long)(b * NN + r0) * HPV3 + h * PVN * 3));
            const float4* bb = reinterpret_cast<const float4*>(g_vp0 + ((long)(b * NN + r1) * HPV3 + h * PVN * 3));
            const float4* cc = reinterpret_cast<const float4*>(g_vp0 + ((long)(b * NN + r2) * HPV3 + h * PVN * 3));
#pragma unroll
            for (int c = 0; c < 6; c++) {
                float4 v = pool ? avg3f4(a[c], bb[c], cc[c]) : a[c];
                lp[c*4+0] = v.x; lp[c*4+1] = v.y; lp[c*4+2] = v.z; lp[c*4+3] = v.w;
            }
            float gp[PVN * 3];
#pragma unroll
            for (int p = 0; p < PVN; p++) {
                float lx = lp[p*3+0], ly = lp[p*3+1], lz = lp[p*3+2];
                gp[p*3+0] = R[0]*lx + R[1]*ly + R[2]*lz + tr[0];
                gp[p*3+1] = R[3]*lx + R[4]*ly + R[5]*lz + tr[1];
                gp[p*3+2] = R[6]*lx + R[7]*ly + R[8]*lz + tr[2];
            }
            float4* dst = reinterpret_cast<float4*>(g_vp + ((long)rt * HPV3 + h * PVN * 3));
#pragma unroll
            for (int c = 0; c < 6; c++)
                dst[c] = make_float4(gp[c*4+0], gp[c*4+1], gp[c*4+2], gp[c*4+3]);
        }
        return;
    }
    int k = idx2 - KV_TOT;
    if (k >= Q_TOT) return;
    int h = k % HH;
    int row = k / HH;
    int b = row / PROW, i = row % PROW;
    int ridx = b * TT + NPAD + i;
    float R[9], tr[3];
#pragma unroll
    for (int r = 0; r < 9; r++) R[r] = g_r_all[ridx * 9 + r];
#pragma unroll
    for (int r = 0; r < 3; r++) tr[r] = g_t_all[ridx * 3 + r];
    float lp[PQN * 3];
    float4* qp4 = reinterpret_cast<float4*>(g_qp + ((long)row * HPQ3 + h * PQN * 3));
#pragma unroll
    for (int c = 0; c < 3; c++) {
        float4 v = qp4[c];
        lp[c*4+0] = v.x; lp[c*4+1] = v.y; lp[c*4+2] = v.z; lp[c*4+3] = v.w;
    }
    float gp[PQN * 3];
#pragma unroll
    for (int p = 0; p < PQN; p++) {
        float lx = lp[p*3+0], ly = lp[p*3+1], lz = lp[p*3+2];
        gp[p*3+0] = R[0]*lx + R[1]*ly + R[2]*lz + tr[0];
        gp[p*3+1] = R[3]*lx + R[4]*ly + R[5]*lz + tr[1];
        gp[p*3+2] = R[6]*lx + R[7]*ly + R[8]*lz + tr[2];
    }
#pragma unroll
    for (int c = 0; c < 3; c++)
        qp4[c] = make_float4(gp[c*4+0], gp[c*4+1], gp[c*4+2], gp[c*4+3]);
}

// ---------------------------------------------------------------------------
// Split-KV attention: grid (B*H, PROW/64, ATTS=8), 64 threads.
// ---------------------------------------------------------------------------
#define TJ 32
#define ATH 64
__global__ void attn_split_kernel(const float* __restrict__ gamma) {
    int bh = blockIdx.x;
    int b = bh / HH, h = bh % HH;
    int i = blockIdx.y * ATH + threadIdx.x;
    int sp = blockIdx.z;
    int tid = threadIdx.x;

    int j_begin = sp * ACHUNK;
    int j_end = j_begin + ACHUNK;
    if (j_end > TT) j_end = TT;

    __shared__ __align__(16) float k_s [TJ][CC];
    __shared__ __align__(16) float v_s [TJ][CC];
    __shared__ __align__(16) float kg_s[TJ][PQN * 3];
    __shared__ __align__(16) float vg_s[TJ][PVN * 3];
    __shared__ float sk_s[TJ];

    int qrow = b * PROW + i;
    float q[CC], qg[PQN * 3];
    {
        const float4* q4 = reinterpret_cast<const float4*>(g_q + (long)qrow * HC + h * CC);
#pragma unroll
        for (int c = 0; c < 4; c++) {
            float4 v = q4[c];
            q[c*4+0] = v.x; q[c*4+1] = v.y; q[c*4+2] = v.z; q[c*4+3] = v.w;
        }
        const float4* g4 = reinterpret_cast<const float4*>(g_qp + (long)qrow * HPQ3 + h * PQN * 3);
#pragma unroll
        for (int c = 0; c < 3; c++) {
            float4 v = g4[c];
            qg[c*4+0] = v.x; qg[c*4+1] = v.y; qg[c*4+2] = v.z; qg[c*4+3] = v.w;
        }
    }
    float sq = 0.f;
#pragma unroll
    for (int x = 0; x < PQN * 3; x++) sq += qg[x] * qg[x];

    float gm = gamma[h];
    float gcoef = logf(1.f + __expf(gm)) * WC_HALF;

    float mrun = -1e30f, lrun = 0.f;
    float ao[CC], ag[PVN * 3];
#pragma unroll
    for (int c = 0; c < CC; c++) ao[c] = 0.f;
#pragma unroll
    for (int x = 0; x < PVN * 3; x++) ag[x] = 0.f;

    for (int j0 = j_begin; j0 < j_end; j0 += TJ) {
        __syncthreads();
        for (int x = tid; x < TJ * 4; x += ATH) {
            int j = x >> 2, c4 = x & 3;
            int jj = j0 + j;
            float4 v = (jj < TT)
                ? reinterpret_cast<const float4*>(g_k + ((long)(b * TT + jj) * HC + h * CC))[c4]
                : make_float4(0.f, 0.f, 0.f, 0.f);
            reinterpret_cast<float4*>(&k_s[j][0])[c4] = v;
        }
        for (int x = tid; x < TJ * 4; x += ATH) {
            int j = x >> 2, c4 = x & 3;
            int jj = j0 + j;
            float4 v = (jj < TT)
                ? reinterpret_cast<const float4*>(g_v + ((long)(b * TT + jj) * HC + h * CC))[c4]
                : make_float4(0.f, 0.f, 0.f, 0.f);
            reinterpret_cast<float4*>(&v_s[j][0])[c4] = v;
        }
        for (int x = tid; x < TJ * 3; x += ATH) {
            int j = x / 3, c4 = x % 3;
            int jj = j0 + j;
            float4 v = (jj < TT)
                ? reinterpret_cast<const float4*>(g_kp + ((long)(b * TT + jj) * HPQ3 + h * PQN * 3))[c4]
                : make_float4(0.f, 0.f, 0.f, 0.f);
            reinterpret_cast<float4*>(&kg_s[j][0])[c4] = v;
        }
        for (int x = tid; x < TJ * 6; x += ATH) {
            int j = x / 6, c4 = x % 6;
            int jj = j0 + j;
            float4 v = (jj < TT)
                ? reinterpret_cast<const float4*>(g_vp + ((long)(b * TT + jj) * HPV3 + h * PVN * 3))[c4]
                : make_float4(0.f, 0.f, 0.f, 0.f);
            reinterpret_cast<float4*>(&vg_s[j][0])[c4] = v;
        }
        for (int x = tid; x < TJ; x += ATH) {
            int jj = j0 + x;
            sk_s[x] = (jj < TT) ? g_sk[(long)(b * TT + jj) * HH + h] : 0.f;
        }
        __syncthreads();

        int nv = j_end - j0;
        if (nv > TJ) nv = TJ;

        float logit[TJ];
        float tmax = -1e30f;
#pragma unroll
        for (int jj = 0; jj < TJ; jj++) {
            float qk = 0.f;
            const float4* k4 = reinterpret_cast<const float4*>(&k_s[jj][0]);
#pragma unroll
            for (int c = 0; c < 4; c++) {
                float4 kv = k4[c];
                qk += q[c*4+0] * kv.x + q[c*4+1] * kv.y + q[c*4+2] * kv.z + q[c*4+3] * kv.w;
            }
            float dt = 0.f;
            const float4* g4 = reinterpret_cast<const float4*>(&kg_s[jj][0]);
#pragma unroll
            for (int c = 0; c < 3; c++) {
                float4 kv = g4[c];
                dt += qg[c*4+0] * kv.x + qg[c*4+1] * kv.y + qg[c*4+2] * kv.z + qg[c*4+3] * kv.w;
            }
            float d2 = sq + sk_s[jj] - 2.f * dt;
            float lg = C1 * qk - gcoef * d2;
            logit[jj] = (jj < nv) ? lg : -1e30f;
            tmax = fmaxf(tmax, logit[jj]);
        }
        float mn = fmaxf(mrun, tmax);
        float corr = __expf(mrun - mn);
        lrun *= corr;
#pragma unroll
        for (int c = 0; c < CC; c++) ao[c] *= corr;
#pragma unroll
        for (int x = 0; x < PVN * 3; x++) ag[x] *= corr;
#pragma unroll
        for (int jj = 0; jj < TJ; jj++) {
            float e = __expf(logit[jj] - mn);
            lrun += e;
            const float4* v4 = reinterpret_cast<const float4*>(&v_s[jj][0]);
#pragma unroll
            for (int c = 0; c < 4; c++) {
                float4 vv = v4[c];
                ao[c*4+0] += e * vv.x; ao[c*4+1] += e * vv.y;
                ao[c*4+2] += e * vv.z; ao[c*4+3] += e * vv.w;
            }
            const float4* g4 = reinterpret_cast<const float4*>(&vg_s[jj][0]);
#pragma unroll
            for (int c = 0; c < 6; c++) {
                float4 vv = g4[c];
                ag[c*4+0] += e * vv.x; ag[c*4+1] += e * vv.y;
                ag[c*4+2] += e * vv.z; ag[c*4+3] += e * vv.w;
            }
        }
        mrun = mn;
    }

    int p = (qrow * HH + h) * ATTS + sp;
    g_pm[p] = mrun;
    g_pl[p] = lrun;
#pragma unroll
    for (int c = 0; c < CC; c++) g_po[(long)p * CC + c] = ao[c];
#pragma unroll
    for (int x = 0; x < PVN * 3; x++) g_pg[(long)p * (PVN * 3) + x] = ag[x];
}

// ---------------------------------------------------------------------------
// Combine split partials + build oc rows. One thread per (b,i,h).
// ---------------------------------------------------------------------------
__global__ void combine_oc_kernel() {
    int idx = blockIdx.x * blockDim.x + threadIdx.x;
    if (idx >= BB * PROW * HH) return;
    int h = idx % HH;
    int row = idx / HH;
    int b = row / PROW, i = row % PROW;
    int p0 = idx * ATTS;

    float m = -1e30f;
#pragma unroll
    for (int s = 0; s < ATTS; s++) m = fmaxf(m, g_pm[p0 + s]);
    float L = 0.f;
    float o[CC], g[PVN * 3];
#pragma unroll
    for (int c = 0; c < CC; c++) o[c] = 0.f;
#pragma unroll
    for (int x = 0; x < PVN * 3; x++) g[x] = 0.f;
#pragma unroll
    for (int s = 0; s < ATTS; s++) {
        float w = __expf(g_pm[p0 + s] - m);
        L += g_pl[p0 + s] * w;
        const float* po = g_po + (long)(p0 + s) * CC;
        const float* pg = g_pg + (long)(p0 + s) * (PVN * 3);
#pragma unroll
        for (int c = 0; c < CC; c++) o[c] += w * po[c];
#pragma unroll
        for (int x = 0; x < PVN * 3; x++) g[x] += w * pg[x];
    }
    float inv = 1.f / L;
#pragma unroll
    for (int c = 0; c < CC; c++) o[c] *= inv;
#pragma unroll
    for (int x = 0; x < PVN * 3; x++) g[x] *= inv;

    int ridx = b * TT + NPAD + i;
    float R[9], tr[3];
#pragma unroll
    for (int r = 0; r < 9; r++) R[r] = g_r_all[ridx * 9 + r];
#pragma unroll
    for (int r = 0; r < 3; r++) tr[r] = g_t_all[ridx * 3 + r];

#pragma unroll
    for (int c = 0; c < CC; c++)
        g_oc[(long)row * OCW + h * CC + c] = o[c];

#pragma unroll
    for (int pp = 0; pp < PVN; pp++) {
        float gx = g[pp * 3 + 0] - tr[0];
        float gy = g[pp * 3 + 1] - tr[1];
        float gz = g[pp * 3 + 2] - tr[2];
        float lx = R[0] * gx + R[3] * gy + R[6] * gz;
        float ly = R[1] * gx + R[4] * gy + R[7] * gz;
        float lz = R[2] * gx + R[5] * gy + R[8] * gz;
        g_oc[(long)row * OCW + HC + h * PVN * 3 + pp * 3 + 0] = lx;
        g_oc[(long)row * OCW + HC + h * PVN * 3 + pp * 3 + 1] = ly;
        g_oc[(long)row * OCW + HC + h * PVN * 3 + pp * 3 + 2] = lz;
        g_oc[(long)row * OCW + HC + HPV3 + h * PVN + pp] =
            sqrtf(lx * lx + ly * ly + lz * lz + 1e-8f);
    }
}

// ---------------------------------------------------------------------------
// Finalize: warp per row.
// ---------------------------------------------------------------------------
__global__ void finalize_kernel(const float* __restrict__ bupd,
                                float* __restrict__ out) {
    int gw = (blockIdx.x * blockDim.x + threadIdx.x) >> 5;
    int lane = threadIdx.x & 31;
    if (gw >= BB * PROW) return;
    int row = gw;
    int b = row / PROW, i = row % PROW;
    int ridx = b * TT + NPAD + i;

    float acc[6] = {0.f, 0.f, 0.f, 0.f, 0.f, 0.f};
    const float* ocr = g_oc + (long)row * OCW;
    for (int k = lane; k < OCW; k += 32) {
        float v = ocr[k];
#pragma unroll
        for (int j = 0; j < 6; j++) acc[j] += v * g_wfold[j * OCW + k];
    }
#pragma unroll
    for (int off = 16; off > 0; off >>= 1)
#pragma unroll
        for (int j = 0; j < 6; j++)
            acc[j] += __shfl_down_sync(0xffffffffu, acc[j], off);
    if (lane != 0) return;

    float u[6];
#pragma unroll
    for (int j = 0; j < 6; j++) u[j] = acc[j] + bupd[j];

    float bq = u[0], cq = u[1], dq = u[2];
    float ninv = rsqrtf(1.f + bq * bq + cq * cq + dq * dq);
    float w = ninv, x = bq * ninv, y = cq * ninv, z = dq * ninv;
    float Ru[9];
    Ru[0] = 1.f - 2.f * (y * y + z * z); Ru[1] = 2.f * (x * y - w * z); Ru[2] = 2.f * (x * z + w * y);
    Ru[3] = 2.f * (x * y + w * z); Ru[4] = 1.f - 2.f * (x * x + z * z); Ru[5] = 2.f * (y * z - w * x);
    Ru[6] = 2.f * (x * z - w * y); Ru[7] = 2.f * (y * z + w * x); Ru[8] = 1.f - 2.f * (x * x + y * y);

    float R[9];
#pragma unroll
    for (int r = 0; r < 9; r++) R[r] = g_r_all[ridx * 9 + r];

    float Rn[9];
#pragma unroll
    for (int r = 0; r < 3; r++)
#pragma unroll
        for (int c = 0; c < 3; c++) {
            float a = 0.f;
#pragma unroll
            for (int k = 0; k < 3; k++) a += R[r * 3 + k] * Ru[k * 3 + c];
            Rn[r * 3 + c] = a;
        }

    out[row * 3 + 0] = R[0] * u[3] + R[1] * u[4] + R[2] * u[5] + g_t_all[ridx * 3 + 0];
    out[row * 3 + 1] = R[3] * u[3] + R[4] * u[4] + R[5] * u[5] + g_t_all[ridx * 3 + 1];
    out[row * 3 + 2] = R[6] * u[3] + R[7] * u[4] + R[8] * u[5] + g_t_all[ridx * 3 + 2];
    float* rout = out + BB * PROW * 3;
#pragma unroll
    for (int r = 0; r < 9; r++) rout[row * 9 + r] = Rn[r];
}

// ---------------------------------------------------------------------------
extern "C" void kernel_launch(void* const* d_in, const int* in_sizes, int n_in,
                              void* d_out, int out_size) {
    const float* trans = (const float*)d_in[0];
    const float* rots  = (const float*)d_in[1];
    const float* s     = (const float*)d_in[2];
    const float* wq    = (const float*)d_in[3];
    const float* wk    = (const float*)d_in[4];
    const float* wv    = (const float*)d_in[5];
    const float* wqp   = (const float*)d_in[6];
    const float* wkp   = (const float*)d_in[7];
    const float* wvp   = (const float*)d_in[8];
    const float* gamma = (const float*)d_in[9];
    const float* wout  = (const float*)d_in[10];
    const float* wupd  = (const float*)d_in[11];
    const float* bupd  = (const float*)d_in[12];
    float* out = (float*)d_out;

    float *p_s_pool, *p_k0, *p_v0, *p_kp0, *p_vp0, *p_q, *p_qp;
    cudaGetSymbolAddress((void**)&p_s_pool, g_s_pool);
    cudaGetSymbolAddress((void**)&p_k0, g_k0);
    cudaGetSymbolAddress((void**)&p_v0, g_v0);
    cudaGetSymbolAddress((void**)&p_kp0, g_kp0);
    cudaGetSymbolAddress((void**)&p_vp0, g_vp0);
    cudaGetSymbolAddress((void**)&p_q, g_q);
    cudaGetSymbolAddress((void**)&p_qp, g_qp);

    // 1. prep
    prep_all_kernel<<<(SP_TOT + TR_TOT + 255) / 256, 256>>>(s, trans, rots);

    // 2. projection GEMMs (double-buffered)
    TaskPack P;
    int Mraw = BB * NN;
    int Mpool = BB * PROW;
    auto setTask = [&](int ti, const float* A, const float* B, float* C,
                       int M, int N, int K) {
        P.t[ti].A = A; P.t[ti].B = B; P.t[ti].C = C;
        P.t[ti].M = M; P.t[ti].N = N; P.t[ti].K = K;
        P.t[ti].gx = (N + GBN - 1) / GBN;
    };
    setTask(0, s, wk,  p_k0,  Mraw, HC,   CSD);
    setTask(1, s, wv,  p_v0,  Mraw, HC,   CSD);
    setTask(2, s, wkp, p_kp0, Mraw, HPQ3, CSD);
    setTask(3, s, wvp, p_vp0, Mraw, HPV3, CSD);
    setTask(4, p_s_pool, wq,  p_q,  Mpool, HC,   CSD);
    setTask(5, p_s_pool, wqp, p_qp, Mpool, HPQ3, CSD);
    P.ofs[0] = 0;
    for (int ti = 0; ti < NTASK; ti++) {
        int gy = (P.t[ti].M + GBM - 1) / GBM;
        P.ofs[ti + 1] = P.ofs[ti] + P.t[ti].gx * gy;
    }
    mgemm_kernel<<<P.ofs[NTASK], 256>>>(P);

    // 3. weight fold
    fold_w_kernel<<<(OCW * 32 + 255) / 256, 256>>>(wout, wupd);

    // 4. expand + transforms (restructured)
    expand_transform_kernel<<<(KVCH + KV_TOT + Q_TOT + 255) / 256, 256>>>();

    // 5. split-KV attention (ATTS=8, 64 threads)
    attn_split_kernel<<<dim3(BB * HH, PROW / ATH, ATTS), ATH>>>(gamma);

    // 6. combine + build oc
    combine_oc_kernel<<<(BB * PROW * HH + 255) / 256, 256>>>();

    // 7. finalize
    finalize_kernel<<<(BB * PROW * 32 + 255) / 256, 256>>>(bupd, out);
}

// round 8
// speedup vs baseline: 1.1630x; 1.1630x over previous
#include <cuda_runtime.h>
#include <math.h>

// Problem constants
#define BB 2
#define NN 1024
#define CSD 384
#define HH 12
#define CC 16
#define PQN 4
#define PVN 8
#define NPAD 1026        // N + 2*PAD
#define PROW 512         // num_pool
#define TT 1538          // NPAD + PROW
#define HC 192           // H*C
#define HPQ3 144         // H*PQ*3
#define HPV3 288         // H*PV*3
#define OCW 576          // HC + HPV3 + H*PV
#define ATTS 4           // split-KV factor (proven)
#define ACHUNK ((TT + ATTS - 1) / ATTS)   // 385

#define C1 0.176776695f       // w_l * (1/sqrt(C))
#define WC_HALF 0.117851130f  // w_c/2

typedef unsigned long long u64;

// packed f32x2 helpers (Blackwell sm_100a+)
__device__ __forceinline__ void fma2(u64 &d, u64 a, u64 b) {
    asm("fma.rn.f32x2 %0, %1, %2, %0;" : "+l"(d) : "l"(a), "l"(b));
}
__device__ __forceinline__ void mul2ip(u64 &d, u64 a) {
    asm("mul.rn.f32x2 %0, %0, %1;" : "+l"(d) : "l"(a));
}
__device__ __forceinline__ u64 pack2(float lo, float hi) {
    u64 r; asm("mov.b64 %0, {%1, %2};" : "=l"(r) : "f"(lo), "f"(hi)); return r;
}
__device__ __forceinline__ void unpack2(u64 v, float &lo, float &hi) {
    asm("mov.b64 {%0, %1}, %2;" : "=f"(lo), "=f"(hi) : "l"(v));
}

// Scratch (device globals)
__device__ float g_s_pool[BB*PROW*CSD];
__device__ float g_t_all[BB*TT*3];
__device__ float g_r_all[BB*TT*9];
__device__ float g_k0 [BB*NN*HC];
__device__ float g_v0 [BB*NN*HC];
__device__ float g_kp0[BB*NN*HPQ3];
__device__ float g_vp0[BB*NN*HPV3];
__device__ float g_k  [BB*TT*HC];
__device__ float g_v  [BB*TT*HC];
__device__ float g_kp [BB*TT*HPQ3];
__device__ float g_vp [BB*TT*HPV3];
__device__ float g_sk [BB*TT*HH];
__device__ float g_q  [BB*PROW*HC];
__device__ float g_qp [BB*PROW*HPQ3];
__device__ float g_oc [BB*PROW*OCW];
__device__ float g_wfold[6*OCW];

#define NPART (BB*PROW*HH*ATTS)
__device__ float g_pm[NPART];
__device__ float g_pl[NPART];
__device__ float g_po[NPART*CC];
__device__ float g_pg[NPART*PVN*3];

__device__ __forceinline__ int clampsrc(int e) {
    int v = e - 1;
    return v < 0 ? 0 : (v > NN - 1 ? NN - 1 : v);
}

// ---------------------------------------------------------------------------
// Prep: pooled s rows + t_all / r_all
// ---------------------------------------------------------------------------
#define SP_TOT (BB*PROW*CSD)
#define TR_TOT (BB*TT*12)
__global__ void prep_all_kernel(const float* __restrict__ s,
                                const float* __restrict__ trans,
                                const float* __restrict__ rots) {
    int idx = blockIdx.x * blockDim.x + threadIdx.x;
    if (idx < SP_TOT) {
        int c = idx % CSD;
        int bp = idx / CSD;
        int p = bp % PROW;
        int b = bp / PROW;
        g_s_pool[idx] = (s[(b * NN + clampsrc(2 * p    )) * CSD + c]
                       + s[(b * NN + clampsrc(2 * p + 1)) * CSD + c]
                       + s[(b * NN + clampsrc(2 * p + 2)) * CSD + c]) * (1.f / 3.f);
        return;
    }
    int k = idx - SP_TOT;
    if (k >= TR_TOT) return;
    int d = k % 12;
    int bt = k / 12;
    int t = bt % TT;
    int b = bt / TT;
    if (d < 3) {
        float val;
        if (t < NPAD) {
            val = trans[(b * NN + clampsrc(t)) * 3 + d];
        } else {
            int p = t - NPAD;
            val = (trans[(b * NN + clampsrc(2 * p    )) * 3 + d]
                 + trans[(b * NN + clampsrc(2 * p + 1)) * 3 + d]
                 + trans[(b * NN + clampsrc(2 * p + 2)) * 3 + d]) * (1.f / 3.f);
        }
        g_t_all[(b * TT + t) * 3 + d] = val;
    } else {
        int r = d - 3;
        float val;
        if (t < NPAD) {
            val = rots[(b * NN + clampsrc(t)) * 9 + r];
        } else {
            int p = t - NPAD;
            val = (rots[(b * NN + clampsrc(2 * p    )) * 9 + r]
                 + rots[(b * NN + clampsrc(2 * p + 1)) * 9 + r]
                 + rots[(b * NN + clampsrc(2 * p + 2)) * 9 + r]) * (1.f / 3.f);
        }
        g_r_all[(b * TT + t) * 9 + r] = val;
    }
}

// ---------------------------------------------------------------------------
// Fused multi-task SGEMM: tile 64x64, BK=16, 256 threads, 4x4/thread.
// (round-5 proven: single-buffered)
// ---------------------------------------------------------------------------
#define NTASK 6
struct GemmTask {
    const float* A;
    const float* B;
    float* C;
    int M, N, K, gx;
};
struct TaskPack {
    GemmTask t[NTASK];
    int ofs[NTASK + 1];
};

#define GBM 64
#define GBN 64
#define GBK 16
__global__ void mgemm_kernel(TaskPack P) {
    int bid = blockIdx.x;
    int ti = 0;
#pragma unroll
    for (int x = 0; x < NTASK - 1; x++)
        if (bid >= P.ofs[x + 1]) ti = x + 1;
    GemmTask tk = P.t[ti];
    int lb = bid - P.ofs[ti];
    int bx = lb % tk.gx, by = lb / tk.gx;

    __shared__ float As[GBK][GBM];
    __shared__ float Bs[GBK][GBN];
    int tid = threadIdx.x;
    int tx = tid % 16, ty = tid / 16;
    int row0 = by * GBM;
    int col0 = bx * GBN;
    const float* A = tk.A;
    const float* Bm = tk.B;
    int M = tk.M, Nn = tk.N, K = tk.K;

    float acc[4][4];
#pragma unroll
    for (int i = 0; i < 4; i++)
#pragma unroll
        for (int j = 0; j < 4; j++) acc[i][j] = 0.f;

    for (int k0 = 0; k0 < K; k0 += GBK) {
#pragma unroll
        for (int x = 0; x < (GBM * GBK) / 256; x++) {
            int li = tid + x * 256;
            int m = li / GBK, kk = li % GBK;
            int gm = row0 + m;
            As[kk][m] = (gm < M) ? A[(long)gm * K + k0 + kk] : 0.f;
        }
#pragma unroll
        for (int x = 0; x < (GBK * GBN) / 256; x++) {
            int li = tid + x * 256;
            int kk = li / GBN, n = li % GBN;
            int gn = col0 + n;
            Bs[kk][n] = (gn < Nn) ? Bm[(long)(k0 + kk) * Nn + gn] : 0.f;
        }
        __syncthreads();
#pragma unroll
        for (int kk = 0; kk < GBK; kk++) {
            float a[4], bvals[4];
#pragma unroll
            for (int i = 0; i < 4; i++) a[i] = As[kk][ty * 4 + i];
#pragma unroll
            for (int j = 0; j < 4; j++) bvals[j] = Bs[kk][tx * 4 + j];
#pragma unroll
            for (int i = 0; i < 4; i++)
#pragma unroll
                for (int j = 0; j < 4; j++) acc[i][j] += a[i] * bvals[j];
        }
        __syncthreads();
    }
#pragma unroll
    for (int i = 0; i < 4; i++) {
        int gm = row0 + ty * 4 + i;
        if (gm >= M) continue;
#pragma unroll
        for (int j = 0; j < 4; j++) {
            int gn = col0 + tx * 4 + j;
            if (gn < Nn) tk.C[(long)gm * Nn + gn] = acc[i][j];
        }
    }
}

// ---------------------------------------------------------------------------
// Weight fold: warp per OCW-row.
// ---------------------------------------------------------------------------
__global__ void fold_w_kernel(const float* __restrict__ wout,
                              const float* __restrict__ wupd) {
    int gw = (blockIdx.x * blockDim.x + threadIdx.x) >> 5;
    int lane = threadIdx.x & 31;
    if (gw >= OCW) return;
    const float* wr = wout + (long)gw * CSD;
    float acc[6] = {0, 0, 0, 0, 0, 0};
    for (int m = lane; m < CSD; m += 32) {
        float w = wr[m];
#pragma unroll
        for (int j = 0; j < 6; j++) acc[j] += w * __ldg(&wupd[m * 6 + j]);
    }
#pragma unroll
    for (int off = 16; off > 0; off >>= 1)
#pragma unroll
        for (int j = 0; j < 6; j++)
            acc[j] += __shfl_down_sync(0xffffffffu, acc[j], off);
    if (lane == 0) {
#pragma unroll
        for (int j = 0; j < 6; j++) g_wfold[j * OCW + gw] = acc[j];
    }
}

// ---------------------------------------------------------------------------
// Expand + transform (round-5 proven structure): per-(b,t,h) threads.
// ---------------------------------------------------------------------------
#define KV_TOT (BB*TT*HH)
#define Q_TOT (BB*PROW*HH)
__device__ __forceinline__ float4 avg3f4(float4 a, float4 b, float4 c) {
    return make_float4((a.x + b.x + c.x) * (1.f / 3.f),
                       (a.y + b.y + c.y) * (1.f / 3.f),
                       (a.z + b.z + c.z) * (1.f / 3.f),
                       (a.w + b.w + c.w) * (1.f / 3.f));
}
__global__ void expand_transform_kernel() {
    int idx = blockIdx.x * blockDim.x + threadIdx.x;
    if (idx < KV_TOT) {
        int h = idx % HH;
        int rt = idx / HH;         // b*TT + t
        int t = rt % TT;
        int b = rt / TT;

        int r0, r1 = 0, r2 = 0;
        bool pool;
        if (t < NPAD) {
            r0 = clampsrc(t);
            pool = false;
        } else {
            int p = t - NPAD;
            r0 = clampsrc(2 * p);
            r1 = clampsrc(2 * p + 1);
            r2 = clampsrc(2 * p + 2);
            pool = true;
        }

        {
            const float4* a = reinterpret_cast<const float4*>(g_k0 + ((long)(b * NN + r0) * HC + h * CC));
            const float4* bb = reinterpret_cast<const float4*>(g_k0 + ((long)(b * NN + r1) * HC + h * CC));
            const float4* cc = reinterpret_cast<const float4*>(g_k0 + ((long)(b * NN + r2) * HC + h * CC));
            float4* dst = reinterpret_cast<float4*>(g_k + ((long)rt * HC + h * CC));
#pragma unroll
            for (int c = 0; c < 4; c++)
                dst[c] = pool ? avg3f4(a[c], bb[c], cc[c]) : a[c];
        }
        {
            const float4* a = reinterpret_cast<const float4*>(g_v0 + ((long)(b * NN + r0) * HC + h * CC));
            const float4* bb = reinterpret_cast<const float4*>(g_v0 + ((long)(b * NN + r1) * HC + h * CC));
            const float4* cc = reinterpret_cast<const float4*>(g_v0 + ((long)(b * NN + r2) * HC + h * CC));
            float4* dst = reinterpret_cast<float4*>(g_v + ((long)rt * HC + h * CC));
#pragma unroll
            for (int c = 0; c < 4; c++)
                dst[c] = pool ? avg3f4(a[c], bb[c], cc[c]) : a[c];
        }

        float R[9], tr[3];
#pragma unroll
        for (int r = 0; r < 9; r++) R[r] = g_r_all[rt * 9 + r];
#pragma unroll
        for (int r = 0; r < 3; r++) tr[r] = g_t_all[rt * 3 + r];

        {
            float lp[PQN * 3];
            const float4* a = reinterpret_cast<const float4*>(g_kp0 + ((long)(b * NN + r0) * HPQ3 + h * PQN * 3));
            const float4* bb = reinterpret_cast<const float4*>(g_kp0 + ((long)(b * NN + r1) * HPQ3 + h * PQN * 3));
            const float4* cc = reinterpret_cast<const float4*>(g_kp0 + ((long)(b * NN + r2) * HPQ3 + h * PQN * 3));
#pragma unroll
            for (int c = 0; c < 3; c++) {
                float4 v = pool ? avg3f4(a[c], bb[c], cc[c]) : a[c];
                lp[c*4+0] = v.x; lp[c*4+1] = v.y; lp[c*4+2] = v.z; lp[c*4+3] = v.w;
            }
            float sk = 0.f;
            float gp[PQN * 3];
#pragma unroll
            for (int p = 0; p < PQN; p++) {
                float lx = lp[p*3+0], ly = lp[p*3+1], lz = lp[p*3+2];
                float gx = R[0]*lx + R[1]*ly + R[2]*lz + tr[0];
                float gy = R[3]*lx + R[4]*ly + R[5]*lz + tr[1];
                float gz = R[6]*lx + R[7]*ly + R[8]*lz + tr[2];
                gp[p*3+0] = gx; gp[p*3+1] = gy; gp[p*3+2] = gz;
                sk += gx*gx + gy*gy + gz*gz;
            }
            g_sk[rt * HH + h] = sk;
            float4* dst = reinterpret_cast<float4*>(g_kp + ((long)rt * HPQ3 + h * PQN * 3));
#pragma unroll
            for (int c = 0; c < 3; c++)
                dst[c] = make_float4(gp[c*4+0], gp[c*4+1], gp[c*4+2], gp[c*4+3]);
        }
        {
            float lp[PVN * 3];
            const float4* a = reinterpret_cast<const float4*>(g_vp0 + ((long)(b * NN + r0) * HPV3 + h * PVN * 3));
            const float4* bb = reinterpret_cast<const float4*>(g_vp0 + ((long)(b * NN + r1) * HPV3 + h * PVN * 3));
            const float4* cc = reinterpret_cast<const float4*>(g_vp0 + ((long)(b * NN + r2) * HPV3 + h * PVN * 3));
#pragma unroll
            for (int c = 0; c < 6; c++) {
                float4 v = pool ? avg3f4(a[c], bb[c], cc[c]) : a[c];
                lp[c*4+0] = v.x; lp[c*4+1] = v.y; lp[c*4+2] = v.z; lp[c*4+3] = v.w;
            }
            float gp[PVN * 3];
#pragma unroll
            for (int p = 0; p < PVN; p++) {
                float lx = lp[p*3+0], ly = lp[p*3+1], lz = lp[p*3+2];
                gp[p*3+0] = R[0]*lx + R[1]*ly + R[2]*lz + tr[0];
                gp[p*3+1] = R[3]*lx + R[4]*ly + R[5]*lz + tr[1];
                gp[p*3+2] = R[6]*lx + R[7]*ly + R[8]*lz + tr[2];
            }
            float4* dst = reinterpret_cast<float4*>(g_vp + ((long)rt * HPV3 + h * PVN * 3));
#pragma unroll
            for (int c = 0; c < 6; c++)
                dst[c] = make_float4(gp[c*4+0], gp[c*4+1], gp[c*4+2], gp[c*4+3]);
        }
        return;
    }
    int k = idx - KV_TOT;
    if (k >= Q_TOT) return;
    int h = k % HH;
    int row = k / HH;
    int b = row / PROW, i = row % PROW;
    int ridx = b * TT + NPAD + i;
    float R[9], tr[3];
#pragma unroll
    for (int r = 0; r < 9; r++) R[r] = g_r_all[ridx * 9 + r];
#pragma unroll
    for (int r = 0; r < 3; r++) tr[r] = g_t_all[ridx * 3 + r];
    float lp[PQN * 3];
    float4* qp4 = reinterpret_cast<float4*>(g_qp + ((long)row * HPQ3 + h * PQN * 3));
#pragma unroll
    for (int c = 0; c < 3; c++) {
        float4 v = qp4[c];
        lp[c*4+0] = v.x; lp[c*4+1] = v.y; lp[c*4+2] = v.z; lp[c*4+3] = v.w;
    }
    float gp[PQN * 3];
#pragma unroll
    for (int p = 0; p < PQN; p++) {
        float lx = lp[p*3+0], ly = lp[p*3+1], lz = lp[p*3+2];
        gp[p*3+0] = R[0]*lx + R[1]*ly + R[2]*lz + tr[0];
        gp[p*3+1] = R[3]*lx + R[4]*ly + R[5]*lz + tr[1];
        gp[p*3+2] = R[6]*lx + R[7]*ly + R[8]*lz + tr[2];
    }
#pragma unroll
    for (int c = 0; c < 3; c++)
        qp4[c] = make_float4(gp[c*4+0], gp[c*4+1], gp[c*4+2], gp[c*4+3]);
}

// ---------------------------------------------------------------------------
// Split-KV attention with packed f32x2 FMA. grid (B*H, PROW/64, ATTS=4),
// 64 threads/block, TJ=32 tiles.
// ---------------------------------------------------------------------------
#define TJ 32
#define ATH 64
__global__ void attn_split_kernel(const float* __restrict__ gamma) {
    int bh = blockIdx.x;
    int b = bh / HH, h = bh % HH;
    int i = blockIdx.y * ATH + threadIdx.x;
    int sp = blockIdx.z;
    int tid = threadIdx.x;

    int j_begin = sp * ACHUNK;
    int j_end = j_begin + ACHUNK;
    if (j_end > TT) j_end = TT;

    __shared__ __align__(16) float k_s [TJ][CC];
    __shared__ __align__(16) float v_s [TJ][CC];
    __shared__ __align__(16) float kg_s[TJ][PQN * 3];
    __shared__ __align__(16) float vg_s[TJ][PVN * 3];
    __shared__ float sk_s[TJ];

    int qrow = b * PROW + i;
    // q and qg as packed f32x2 pairs
    u64 q2[CC / 2], qg2[PQN * 3 / 2];
    {
        const u64* q64 = reinterpret_cast<const u64*>(g_q + (long)qrow * HC + h * CC);
#pragma unroll
        for (int c = 0; c < CC / 2; c++) q2[c] = q64[c];
        const u64* g64 = reinterpret_cast<const u64*>(g_qp + (long)qrow * HPQ3 + h * PQN * 3);
#pragma unroll
        for (int c = 0; c < PQN * 3 / 2; c++) qg2[c] = g64[c];
    }
    float sq;
    {
        u64 a = 0ULL;
#pragma unroll
        for (int c = 0; c < PQN * 3 / 2; c++) fma2(a, qg2[c], qg2[c]);
        float lo, hi; unpack2(a, lo, hi);
        sq = lo + hi;
    }

    float gm = gamma[h];
    float gcoef = logf(1.f + __expf(gm)) * WC_HALF;

    float mrun = -1e30f, lrun = 0.f;
    u64 ao2[CC / 2], ag2[PVN * 3 / 2];
#pragma unroll
    for (int c = 0; c < CC / 2; c++) ao2[c] = 0ULL;
#pragma unroll
    for (int x = 0; x < PVN * 3 / 2; x++) ag2[x] = 0ULL;

    for (int j0 = j_begin; j0 < j_end; j0 += TJ) {
        __syncthreads();
        for (int x = tid; x < TJ * 4; x += ATH) {
            int j = x >> 2, c4 = x & 3;
            int jj = j0 + j;
            float4 v = (jj < TT)
                ? reinterpret_cast<const float4*>(g_k + ((long)(b * TT + jj) * HC + h * CC))[c4]
                : make_float4(0.f, 0.f, 0.f, 0.f);
            reinterpret_cast<float4*>(&k_s[j][0])[c4] = v;
        }
        for (int x = tid; x < TJ * 4; x += ATH) {
            int j = x >> 2, c4 = x & 3;
            int jj = j0 + j;
            float4 v = (jj < TT)
                ? reinterpret_cast<const float4*>(g_v + ((long)(b * TT + jj) * HC + h * CC))[c4]
                : make_float4(0.f, 0.f, 0.f, 0.f);
            reinterpret_cast<float4*>(&v_s[j][0])[c4] = v;
        }
        for (int x = tid; x < TJ * 3; x += ATH) {
            int j = x / 3, c4 = x % 3;
            int jj = j0 + j;
            float4 v = (jj < TT)
                ? reinterpret_cast<const float4*>(g_kp + ((long)(b * TT + jj) * HPQ3 + h * PQN * 3))[c4]
                : make_float4(0.f, 0.f, 0.f, 0.f);
            reinterpret_cast<float4*>(&kg_s[j][0])[c4] = v;
        }
        for (int x = tid; x < TJ * 6; x += ATH) {
            int j = x / 6, c4 = x % 6;
            int jj = j0 + j;
            float4 v = (jj < TT)
                ? reinterpret_cast<const float4*>(g_vp + ((long)(b * TT + jj) * HPV3 + h * PVN * 3))[c4]
                : make_float4(0.f, 0.f, 0.f, 0.f);
            reinterpret_cast<float4*>(&vg_s[j][0])[c4] = v;
        }
        for (int x = tid; x < TJ; x += ATH) {
            int jj = j0 + x;
            sk_s[x] = (jj < TT) ? g_sk[(long)(b * TT + jj) * HH + h] : 0.f;
        }
        __syncthreads();

        int nv = j_end - j0;
        if (nv > TJ) nv = TJ;

        float logit[TJ];
        float tmax = -1e30f;
#pragma unroll
        for (int jj = 0; jj < TJ; jj++) {
            u64 a1 = 0ULL;
            const u64* k64 = reinterpret_cast<const u64*>(&k_s[jj][0]);
#pragma unroll
            for (int c = 0; c < CC / 2; c++) fma2(a1, q2[c], k64[c]);
            u64 a2 = 0ULL;
            const u64* kg64 = reinterpret_cast<const u64*>(&kg_s[jj][0]);
#pragma unroll
            for (int c = 0; c < PQN * 3 / 2; c++) fma2(a2, qg2[c], kg64[c]);
            float l1, h1, l2, h2;
            unpack2(a1, l1, h1);
            unpack2(a2, l2, h2);
            float qk = l1 + h1;
            float dt = l2 + h2;
            float d2 = sq + sk_s[jj] - 2.f * dt;
            float lg = C1 * qk - gcoef * d2;
            logit[jj] = (jj < nv) ? lg : -1e30f;
            tmax = fmaxf(tmax, logit[jj]);
        }
        float mn = fmaxf(mrun, tmax);
        float corr = __expf(mrun - mn);
        lrun *= corr;
        u64 corr2 = pack2(corr, corr);
#pragma unroll
        for (int c = 0; c < CC / 2; c++) mul2ip(ao2[c], corr2);
#pragma unroll
        for (int x = 0; x < PVN * 3 / 2; x++) mul2ip(ag2[x], corr2);
#pragma unroll
        for (int jj = 0; jj < TJ; jj++) {
            float e = __expf(logit[jj] - mn);
            lrun += e;
            u64 ee = pack2(e, e);
            const u64* v64 = reinterpret_cast<const u64*>(&v_s[jj][0]);
#pragma unroll
            for (int c = 0; c < CC / 2; c++) fma2(ao2[c], ee, v64[c]);
            const u64* g64 = reinterpret_cast<const u64*>(&vg_s[jj][0]);
#pragma unroll
            for (int c = 0; c < PVN * 3 / 2; c++) fma2(ag2[c], ee, g64[c]);
        }
        mrun = mn;
    }

    int p = (qrow * HH + h) * ATTS + sp;
    g_pm[p] = mrun;
    g_pl[p] = lrun;
#pragma unroll
    for (int c = 0; c < CC / 2; c++) {
        float lo, hi; unpack2(ao2[c], lo, hi);
        g_po[(long)p * CC + 2*c] = lo;
        g_po[(long)p * CC + 2*c + 1] = hi;
    }
#pragma unroll
    for (int x = 0; x < PVN * 3 / 2; x++) {
        float lo, hi; unpack2(ag2[x], lo, hi);
        g_pg[(long)p * (PVN * 3) + 2*x] = lo;
        g_pg[(long)p * (PVN * 3) + 2*x + 1] = hi;
    }
}

// ---------------------------------------------------------------------------
// Combine split partials + build oc rows. One thread per (b,i,h).
// ---------------------------------------------------------------------------
__global__ void combine_oc_kernel() {
    int idx = blockIdx.x * blockDim.x + threadIdx.x;
    if (idx >= BB * PROW * HH) return;
    int h = idx % HH;
    int row = idx / HH;
    int b = row / PROW, i = row % PROW;
    int p0 = idx * ATTS;

    float m = -1e30f;
#pragma unroll
    for (int s = 0; s < ATTS; s++) m = fmaxf(m, g_pm[p0 + s]);
    float L = 0.f;
    float o[CC], g[PVN * 3];
#pragma unroll
    for (int c = 0; c < CC; c++) o[c] = 0.f;
#pragma unroll
    for (int x = 0; x < PVN * 3; x++) g[x] = 0.f;
#pragma unroll
    for (int s = 0; s < ATTS; s++) {
        float w = __expf(g_pm[p0 + s] - m);
        L += g_pl[p0 + s] * w;
        const float* po = g_po + (long)(p0 + s) * CC;
        const float* pg = g_pg + (long)(p0 + s) * (PVN * 3);
#pragma unroll
        for (int c = 0; c < CC; c++) o[c] += w * po[c];
#pragma unroll
        for (int x = 0; x < PVN * 3; x++) g[x] += w * pg[x];
    }
    float inv = 1.f / L;
#pragma unroll
    for (int c = 0; c < CC; c++) o[c] *= inv;
#pragma unroll
    for (int x = 0; x < PVN * 3; x++) g[x] *= inv;

    int ridx = b * TT + NPAD + i;
    float R[9], tr[3];
#pragma unroll
    for (int r = 0; r < 9; r++) R[r] = g_r_all[ridx * 9 + r];
#pragma unroll
    for (int r = 0; r < 3; r++) tr[r] = g_t_all[ridx * 3 + r];

#pragma unroll
    for (int c = 0; c < CC; c++)
        g_oc[(long)row * OCW + h * CC + c] = o[c];

#pragma unroll
    for (int pp = 0; pp < PVN; pp++) {
        float gx = g[pp * 3 + 0] - tr[0];
        float gy = g[pp * 3 + 1] - tr[1];
        float gz = g[pp * 3 + 2] - tr[2];
        float lx = R[0] * gx + R[3] * gy + R[6] * gz;
        float ly = R[1] * gx + R[4] * gy + R[7] * gz;
        float lz = R[2] * gx + R[5] * gy + R[8] * gz;
        g_oc[(long)row * OCW + HC + h * PVN * 3 + pp * 3 + 0] = lx;
        g_oc[(long)row * OCW + HC + h * PVN * 3 + pp * 3 + 1] = ly;
        g_oc[(long)row * OCW + HC + h * PVN * 3 + pp * 3 + 2] = lz;
        g_oc[(long)row * OCW + HC + HPV3 + h * PVN + pp] =
            sqrtf(lx * lx + ly * ly + lz * lz + 1e-8f);
    }
}

// ---------------------------------------------------------------------------
// Finalize: warp per row.
// ---------------------------------------------------------------------------
__global__ void finalize_kernel(const float* __restrict__ bupd,
                                float* __restrict__ out) {
    int gw = (blockIdx.x * blockDim.x + threadIdx.x) >> 5;
    int lane = threadIdx.x & 31;
    if (gw >= BB * PROW) return;
    int row = gw;
    int b = row / PROW, i = row % PROW;
    int ridx = b * TT + NPAD + i;

    float acc[6] = {0.f, 0.f, 0.f, 0.f, 0.f, 0.f};
    const float* ocr = g_oc + (long)row * OCW;
    for (int k = lane; k < OCW; k += 32) {
        float v = ocr[k];
#pragma unroll
        for (int j = 0; j < 6; j++) acc[j] += v * g_wfold[j * OCW + k];
    }
#pragma unroll
    for (int off = 16; off > 0; off >>= 1)
#pragma unroll
        for (int j = 0; j < 6; j++)
            acc[j] += __shfl_down_sync(0xffffffffu, acc[j], off);
    if (lane != 0) return;

    float u[6];
#pragma unroll
    for (int j = 0; j < 6; j++) u[j] = acc[j] + bupd[j];

    float bq = u[0], cq = u[1], dq = u[2];
    float ninv = rsqrtf(1.f + bq * bq + cq * cq + dq * dq);
    float w = ninv, x = bq * ninv, y = cq * ninv, z = dq * ninv;
    float Ru[9];
    Ru[0] = 1.f - 2.f * (y * y + z * z); Ru[1] = 2.f * (x * y - w * z); Ru[2] = 2.f * (x * z + w * y);
    Ru[3] = 2.f * (x * y + w * z); Ru[4] = 1.f - 2.f * (x * x + z * z); Ru[5] = 2.f * (y * z - w * x);
    Ru[6] = 2.f * (x * z - w * y); Ru[7] = 2.f * (y * z + w * x); Ru[8] = 1.f - 2.f * (x * x + y * y);

    float R[9];
#pragma unroll
    for (int r = 0; r < 9; r++) R[r] = g_r_all[ridx * 9 + r];

    float Rn[9];
#pragma unroll
    for (int r = 0; r < 3; r++)
#pragma unroll
        for (int c = 0; c < 3; c++) {
            float a = 0.f;
#pragma unroll
            for (int k = 0; k < 3; k++) a += R[r * 3 + k] * Ru[k * 3 + c];
            Rn[r * 3 + c] = a;
        }

    out[row * 3 + 0] = R[0] * u[3] + R[1] * u[4] + R[2] * u[5] + g_t_all[ridx * 3 + 0];
    out[row * 3 + 1] = R[3] * u[3] + R[4] * u[4] + R[5] * u[5] + g_t_all[ridx * 3 + 1];
    out[row * 3 + 2] = R[6] * u[3] + R[7] * u[4] + R[8] * u[5] + g_t_all[ridx * 3 + 2];
    float* rout = out + BB * PROW * 3;
#pragma unroll
    for (int r = 0; r < 9; r++) rout[row * 9 + r] = Rn[r];
}

// ---------------------------------------------------------------------------
extern "C" void kernel_launch(void* const* d_in, const int* in_sizes, int n_in,
                              void* d_out, int out_size) {
    const float* trans = (const float*)d_in[0];
    const float* rots  = (const float*)d_in[1];
    const float* s     = (const float*)d_in[2];
    const float* wq    = (const float*)d_in[3];
    const float* wk    = (const float*)d_in[4];
    const float* wv    = (const float*)d_in[5];
    const float* wqp   = (const float*)d_in[6];
    const float* wkp   = (const float*)d_in[7];
    const float* wvp   = (const float*)d_in[8];
    const float* gamma = (const float*)d_in[9];
    const float* wout  = (const float*)d_in[10];
    const float* wupd  = (const float*)d_in[11];
    const float* bupd  = (const float*)d_in[12];
    float* out = (float*)d_out;

    float *p_s_pool, *p_k0, *p_v0, *p_kp0, *p_vp0, *p_q, *p_qp;
    cudaGetSymbolAddress((void**)&p_s_pool, g_s_pool);
    cudaGetSymbolAddress((void**)&p_k0, g_k0);
    cudaGetSymbolAddress((void**)&p_v0, g_v0);
    cudaGetSymbolAddress((void**)&p_kp0, g_kp0);
    cudaGetSymbolAddress((void**)&p_vp0, g_vp0);
    cudaGetSymbolAddress((void**)&p_q, g_q);
    cudaGetSymbolAddress((void**)&p_qp, g_qp);

    // 1. prep
    prep_all_kernel<<<(SP_TOT + TR_TOT + 255) / 256, 256>>>(s, trans, rots);

    // 2. projection GEMMs
    TaskPack P;
    int Mraw = BB * NN;
    int Mpool = BB * PROW;
    auto setTask = [&](int ti, const float* A, const float* B, float* C,
                       int M, int N, int K) {
        P.t[ti].A = A; P.t[ti].B = B; P.t[ti].C = C;
        P.t[ti].M = M; P.t[ti].N = N; P.t[ti].K = K;
        P.t[ti].gx = (N + GBN - 1) / GBN;
    };
    setTask(0, s, wk,  p_k0,  Mraw, HC,   CSD);
    setTask(1, s, wv,  p_v0,  Mraw, HC,   CSD);
    setTask(2, s, wkp, p_kp0, Mraw, HPQ3, CSD);
    setTask(3, s, wvp, p_vp0, Mraw, HPV3, CSD);
    setTask(4, p_s_pool, wq,  p_q,  Mpool, HC,   CSD);
    setTask(5, p_s_pool, wqp, p_qp, Mpool, HPQ3, CSD);
    P.ofs[0] = 0;
    for (int ti = 0; ti < NTASK; ti++) {
        int gy = (P.t[ti].M + GBM - 1) / GBM;
        P.ofs[ti + 1] = P.ofs[ti] + P.t[ti].gx * gy;
    }
    mgemm_kernel<<<P.ofs[NTASK], 256>>>(P);

    // 3. weight fold
    fold_w_kernel<<<(OCW * 32 + 255) / 256, 256>>>(wout, wupd);

    // 4. expand + transforms
    expand_transform_kernel<<<(KV_TOT + Q_TOT + 255) / 256, 256>>>();

    // 5. split-KV attention (f32x2 packed math)
    attn_split_kernel<<<dim3(BB * HH, PROW / ATH, ATTS), ATH>>>(gamma);

    // 6. combine + build oc
    combine_oc_kernel<<<(BB * PROW * HH + 255) / 256, 256>>>();

    // 7. finalize
    finalize_kernel<<<(BB * PROW * 32 + 255) / 256, 256>>>(bupd, out);
}

// round 9
// speedup vs baseline: 1.1733x; 1.0089x over previous
#include <cuda_runtime.h>
#include <math.h>

// Problem constants
#define BB 2
#define NN 1024
#define CSD 384
#define HH 12
#define CC 16
#define PQN 4
#define PVN 8
#define NPAD 1026        // N + 2*PAD
#define PROW 512         // num_pool
#define TT 1538          // NPAD + PROW
#define HC 192           // H*C
#define HPQ3 144         // H*PQ*3
#define HPV3 288         // H*PV*3
#define OCW 576          // HC + HPV3 + H*PV
#define ATTS 4           // split-KV factor (proven)
#define ACHUNK ((TT + ATTS - 1) / ATTS)   // 385

#define C1 0.176776695f       // w_l * (1/sqrt(C))
#define WC_HALF 0.117851130f  // w_c/2

typedef unsigned long long u64;

// packed f32x2 helpers (Blackwell sm_100a+)
__device__ __forceinline__ void fma2(u64 &d, u64 a, u64 b) {
    asm("fma.rn.f32x2 %0, %1, %2, %0;" : "+l"(d) : "l"(a), "l"(b));
}
__device__ __forceinline__ void mul2ip(u64 &d, u64 a) {
    asm("mul.rn.f32x2 %0, %0, %1;" : "+l"(d) : "l"(a));
}
__device__ __forceinline__ u64 pack2(float lo, float hi) {
    u64 r; asm("mov.b64 %0, {%1, %2};" : "=l"(r) : "f"(lo), "f"(hi)); return r;
}
__device__ __forceinline__ void unpack2(u64 v, float &lo, float &hi) {
    asm("mov.b64 {%0, %1}, %2;" : "=f"(lo), "=f"(hi) : "l"(v));
}

// Scratch (device globals)
__device__ float g_s_pool[BB*PROW*CSD];
// pooled-only frames
__device__ float g_tP[BB*PROW*3];
__device__ float g_rP[BB*PROW*9];
// raw-row projections (GEMM outputs)
__device__ float g_k0 [BB*NN*HC];
__device__ float g_v0 [BB*NN*HC];
__device__ float g_kp0[BB*NN*HPQ3];
__device__ float g_vp0[BB*NN*HPV3];
// transformed raw points + raw sk
__device__ float g_kpT[BB*NN*HPQ3];
__device__ float g_vpT[BB*NN*HPV3];
__device__ float g_skR[BB*NN*HH];
// pooled keys/values (averages) + transformed pooled points
__device__ float g_kP [BB*PROW*HC];
__device__ float g_vP [BB*PROW*HC];
__device__ float g_kpP[BB*PROW*HPQ3];
__device__ float g_vpP[BB*PROW*HPV3];
__device__ float g_skP[BB*PROW*HH];
// queries (pooled rows)
__device__ float g_q  [BB*PROW*HC];
__device__ float g_qp [BB*PROW*HPQ3];
__device__ float g_oc [BB*PROW*OCW];
__device__ float g_wfold[6*OCW];

#define NPART (BB*PROW*HH*ATTS)
__device__ float g_pm[NPART];
__device__ float g_pl[NPART];
__device__ float g_po[NPART*CC];
__device__ float g_pg[NPART*PVN*3];

__device__ __forceinline__ int clampsrc(int e) {
    int v = e - 1;
    return v < 0 ? 0 : (v > NN - 1 ? NN - 1 : v);
}

// ---------------------------------------------------------------------------
// Prep: pooled s rows + pooled-only t/r
// ---------------------------------------------------------------------------
#define SP_TOT (BB*PROW*CSD)
#define TRP_TOT (BB*PROW*12)
__global__ void prep_all_kernel(const float* __restrict__ s,
                                const float* __restrict__ trans,
                                const float* __restrict__ rots) {
    int idx = blockIdx.x * blockDim.x + threadIdx.x;
    if (idx < SP_TOT) {
        int c = idx % CSD;
        int bp = idx / CSD;
        int p = bp % PROW;
        int b = bp / PROW;
        g_s_pool[idx] = (s[(b * NN + clampsrc(2 * p    )) * CSD + c]
                       + s[(b * NN + clampsrc(2 * p + 1)) * CSD + c]
                       + s[(b * NN + clampsrc(2 * p + 2)) * CSD + c]) * (1.f / 3.f);
        return;
    }
    int k = idx - SP_TOT;
    if (k >= TRP_TOT) return;
    int d = k % 12;
    int bp = k / 12;
    int p = bp % PROW;
    int b = bp / PROW;
    int r0 = clampsrc(2 * p), r1 = clampsrc(2 * p + 1), r2 = clampsrc(2 * p + 2);
    if (d < 3) {
        g_tP[bp * 3 + d] = (trans[(b * NN + r0) * 3 + d]
                          + trans[(b * NN + r1) * 3 + d]
                          + trans[(b * NN + r2) * 3 + d]) * (1.f / 3.f);
    } else {
        int r = d - 3;
        g_rP[bp * 9 + r] = (rots[(b * NN + r0) * 9 + r]
                          + rots[(b * NN + r1) * 9 + r]
                          + rots[(b * NN + r2) * 9 + r]) * (1.f / 3.f);
    }
}

// ---------------------------------------------------------------------------
// Fused multi-task SGEMM: tile 64x64, BK=16, 256 threads, 4x4/thread.
// ---------------------------------------------------------------------------
#define NTASK 6
struct GemmTask {
    const float* A;
    const float* B;
    float* C;
    int M, N, K, gx;
};
struct TaskPack {
    GemmTask t[NTASK];
    int ofs[NTASK + 1];
};

#define GBM 64
#define GBN 64
#define GBK 16
__global__ void mgemm_kernel(TaskPack P) {
    int bid = blockIdx.x;
    int ti = 0;
#pragma unroll
    for (int x = 0; x < NTASK - 1; x++)
        if (bid >= P.ofs[x + 1]) ti = x + 1;
    GemmTask tk = P.t[ti];
    int lb = bid - P.ofs[ti];
    int bx = lb % tk.gx, by = lb / tk.gx;

    __shared__ float As[GBK][GBM];
    __shared__ float Bs[GBK][GBN];
    int tid = threadIdx.x;
    int tx = tid % 16, ty = tid / 16;
    int row0 = by * GBM;
    int col0 = bx * GBN;
    const float* A = tk.A;
    const float* Bm = tk.B;
    int M = tk.M, Nn = tk.N, K = tk.K;

    float acc[4][4];
#pragma unroll
    for (int i = 0; i < 4; i++)
#pragma unroll
        for (int j = 0; j < 4; j++) acc[i][j] = 0.f;

    for (int k0 = 0; k0 < K; k0 += GBK) {
#pragma unroll
        for (int x = 0; x < (GBM * GBK) / 256; x++) {
            int li = tid + x * 256;
            int m = li / GBK, kk = li % GBK;
            int gm = row0 + m;
            As[kk][m] = (gm < M) ? A[(long)gm * K + k0 + kk] : 0.f;
        }
#pragma unroll
        for (int x = 0; x < (GBK * GBN) / 256; x++) {
            int li = tid + x * 256;
            int kk = li / GBN, n = li % GBN;
            int gn = col0 + n;
            Bs[kk][n] = (gn < Nn) ? Bm[(long)(k0 + kk) * Nn + gn] : 0.f;
        }
        __syncthreads();
#pragma unroll
        for (int kk = 0; kk < GBK; kk++) {
            float a[4], bvals[4];
#pragma unroll
            for (int i = 0; i < 4; i++) a[i] = As[kk][ty * 4 + i];
#pragma unroll
            for (int j = 0; j < 4; j++) bvals[j] = Bs[kk][tx * 4 + j];
#pragma unroll
            for (int i = 0; i < 4; i++)
#pragma unroll
                for (int j = 0; j < 4; j++) acc[i][j] += a[i] * bvals[j];
        }
        __syncthreads();
    }
#pragma unroll
    for (int i = 0; i < 4; i++) {
        int gm = row0 + ty * 4 + i;
        if (gm >= M) continue;
#pragma unroll
        for (int j = 0; j < 4; j++) {
            int gn = col0 + tx * 4 + j;
            if (gn < Nn) tk.C[(long)gm * Nn + gn] = acc[i][j];
        }
    }
}

// ---------------------------------------------------------------------------
// Weight fold: warp per OCW-row.
// ---------------------------------------------------------------------------
__global__ void fold_w_kernel(const float* __restrict__ wout,
                              const float* __restrict__ wupd) {
    int gw = (blockIdx.x * blockDim.x + threadIdx.x) >> 5;
    int lane = threadIdx.x & 31;
    if (gw >= OCW) return;
    const float* wr = wout + (long)gw * CSD;
    float acc[6] = {0, 0, 0, 0, 0, 0};
    for (int m = lane; m < CSD; m += 32) {
        float w = wr[m];
#pragma unroll
        for (int j = 0; j < 6; j++) acc[j] += w * __ldg(&wupd[m * 6 + j]);
    }
#pragma unroll
    for (int off = 16; off > 0; off >>= 1)
#pragma unroll
        for (int j = 0; j < 6; j++)
            acc[j] += __shfl_down_sync(0xffffffffu, acc[j], off);
    if (lane == 0) {
#pragma unroll
        for (int j = 0; j < 6; j++) g_wfold[j * OCW + gw] = acc[j];
    }
}

// ---------------------------------------------------------------------------
// Transform kernel, 4 ranges:
//  R1: raw kp/vp transform + skR, per (b,n,h), rotation read from input rots
//  R2: pooled k/v averages, per float4 chunk
//  R3: pooled kp/vp avg+transform + skP, per (b,p,h)
//  R4: q point transform, per (b,p,h)
// ---------------------------------------------------------------------------
#define RAWPT (BB*NN*HH)
#define POOLKV (BB*PROW*(HC/4)*2)
#define POOLPT (BB*PROW*HH)
#define QPT (BB*PROW*HH)
#define XF_TOT (RAWPT + POOLKV + POOLPT + QPT)

__device__ __forceinline__ float4 avg3f4(float4 a, float4 b, float4 c) {
    return make_float4((a.x + b.x + c.x) * (1.f / 3.f),
                       (a.y + b.y + c.y) * (1.f / 3.f),
                       (a.z + b.z + c.z) * (1.f / 3.f),
                       (a.w + b.w + c.w) * (1.f / 3.f));
}

__global__ void transform_kernel(const float* __restrict__ trans,
                                 const float* __restrict__ rots) {
    int idx = blockIdx.x * blockDim.x + threadIdx.x;
    if (idx < RAWPT) {
        // raw point transform
        int h = idx % HH;
        int rn = idx / HH;          // b*NN + n
        float R[9], tr[3];
#pragma unroll
        for (int r = 0; r < 9; r++) R[r] = rots[rn * 9 + r];
#pragma unroll
        for (int r = 0; r < 3; r++) tr[r] = trans[rn * 3 + r];

        // kp
        {
            const float4* src = reinterpret_cast<const float4*>(g_kp0 + ((long)rn * HPQ3 + h * PQN * 3));
            float lp[PQN * 3];
#pragma unroll
            for (int c = 0; c < 3; c++) {
                float4 v = src[c];
                lp[c*4+0] = v.x; lp[c*4+1] = v.y; lp[c*4+2] = v.z; lp[c*4+3] = v.w;
            }
            float sk = 0.f;
            float gp[PQN * 3];
#pragma unroll
            for (int p = 0; p < PQN; p++) {
                float lx = lp[p*3+0], ly = lp[p*3+1], lz = lp[p*3+2];
                float gx = R[0]*lx + R[1]*ly + R[2]*lz + tr[0];
                float gy = R[3]*lx + R[4]*ly + R[5]*lz + tr[1];
                float gz = R[6]*lx + R[7]*ly + R[8]*lz + tr[2];
                gp[p*3+0] = gx; gp[p*3+1] = gy; gp[p*3+2] = gz;
                sk += gx*gx + gy*gy + gz*gz;
            }
            g_skR[rn * HH + h] = sk;
            float4* dst = reinterpret_cast<float4*>(g_kpT + ((long)rn * HPQ3 + h * PQN * 3));
#pragma unroll
            for (int c = 0; c < 3; c++)
                dst[c] = make_float4(gp[c*4+0], gp[c*4+1], gp[c*4+2], gp[c*4+3]);
        }
        // vp
        {
            const float4* src = reinterpret_cast<const float4*>(g_vp0 + ((long)rn * HPV3 + h * PVN * 3));
            float lp[PVN * 3];
#pragma unroll
            for (int c = 0; c < 6; c++) {
                float4 v = src[c];
                lp[c*4+0] = v.x; lp[c*4+1] = v.y; lp[c*4+2] = v.z; lp[c*4+3] = v.w;
            }
            float gp[PVN * 3];
#pragma unroll
            for (int p = 0; p < PVN; p++) {
                float lx = lp[p*3+0], ly = lp[p*3+1], lz = lp[p*3+2];
                gp[p*3+0] = R[0]*lx + R[1]*ly + R[2]*lz + tr[0];
                gp[p*3+1] = R[3]*lx + R[4]*ly + R[5]*lz + tr[1];
                gp[p*3+2] = R[6]*lx + R[7]*ly + R[8]*lz + tr[2];
            }
            float4* dst = reinterpret_cast<float4*>(g_vpT + ((long)rn * HPV3 + h * PVN * 3));
#pragma unroll
            for (int c = 0; c < 6; c++)
                dst[c] = make_float4(gp[c*4+0], gp[c*4+1], gp[c*4+2], gp[c*4+3]);
        }
        return;
    }
    int i2 = idx - RAWPT;
    if (i2 < POOLKV) {
        // pooled k/v average, per float4 chunk
        int c = i2 % (HC / 4);
        int rest = i2 / (HC / 4);
        int rp = rest % (BB * PROW);    // b*PROW + p
        int sel = rest / (BB * PROW);   // 0=k, 1=v
        int p = rp % PROW;
        int b = rp / PROW;
        int r0 = clampsrc(2 * p), r1 = clampsrc(2 * p + 1), r2 = clampsrc(2 * p + 2);
        const float* srcbase = sel ? g_v0 : g_k0;
        float* dstbase = sel ? g_vP : g_kP;
        float4 a = reinterpret_cast<const float4*>(srcbase + ((long)(b * NN + r0) * HC))[c];
        float4 bb = reinterpret_cast<const float4*>(srcbase + ((long)(b * NN + r1) * HC))[c];
        float4 cc = reinterpret_cast<const float4*>(srcbase + ((long)(b * NN + r2) * HC))[c];
        reinterpret_cast<float4*>(dstbase + ((long)rp * HC))[c] = avg3f4(a, bb, cc);
        return;
    }
    int i3 = i2 - POOLKV;
    if (i3 < POOLPT) {
        // pooled points: avg + transform with pooled frame
        int h = i3 % HH;
        int rp = i3 / HH;
        int p = rp % PROW;
        int b = rp / PROW;
        int r0 = clampsrc(2 * p), r1 = clampsrc(2 * p + 1), r2 = clampsrc(2 * p + 2);
        float R[9], tr[3];
#pragma unroll
        for (int r = 0; r < 9; r++) R[r] = g_rP[rp * 9 + r];
#pragma unroll
        for (int r = 0; r < 3; r++) tr[r] = g_tP[rp * 3 + r];

        {
            float lp[PQN * 3];
            const float4* a = reinterpret_cast<const float4*>(g_kp0 + ((long)(b * NN + r0) * HPQ3 + h * PQN * 3));
            const float4* bb = reinterpret_cast<const float4*>(g_kp0 + ((long)(b * NN + r1) * HPQ3 + h * PQN * 3));
            const float4* cc = reinterpret_cast<const float4*>(g_kp0 + ((long)(b * NN + r2) * HPQ3 + h * PQN * 3));
#pragma unroll
            for (int c = 0; c < 3; c++) {
                float4 v = avg3f4(a[c], bb[c], cc[c]);
                lp[c*4+0] = v.x; lp[c*4+1] = v.y; lp[c*4+2] = v.z; lp[c*4+3] = v.w;
            }
            float sk = 0.f;
            float gp[PQN * 3];
#pragma unroll
            for (int pp = 0; pp < PQN; pp++) {
                float lx = lp[pp*3+0], ly = lp[pp*3+1], lz = lp[pp*3+2];
                float gx = R[0]*lx + R[1]*ly + R[2]*lz + tr[0];
                float gy = R[3]*lx + R[4]*ly + R[5]*lz + tr[1];
                float gz = R[6]*lx + R[7]*ly + R[8]*lz + tr[2];
                gp[pp*3+0] = gx; gp[pp*3+1] = gy; gp[pp*3+2] = gz;
                sk += gx*gx + gy*gy + gz*gz;
            }
            g_skP[rp * HH + h] = sk;
            float4* dst = reinterpret_cast<float4*>(g_kpP + ((long)rp * HPQ3 + h * PQN * 3));
#pragma unroll
            for (int c = 0; c < 3; c++)
                dst[c] = make_float4(gp[c*4+0], gp[c*4+1], gp[c*4+2], gp[c*4+3]);
        }
        {
            float lp[PVN * 3];
            const float4* a = reinterpret_cast<const float4*>(g_vp0 + ((long)(b * NN + r0) * HPV3 + h * PVN * 3));
            const float4* bb = reinterpret_cast<const float4*>(g_vp0 + ((long)(b * NN + r1) * HPV3 + h * PVN * 3));
            const float4* cc = reinterpret_cast<const float4*>(g_vp0 + ((long)(b * NN + r2) * HPV3 + h * PVN * 3));
#pragma unroll
            for (int c = 0; c < 6; c++) {
                float4 v = avg3f4(a[c], bb[c], cc[c]);
                lp[c*4+0] = v.x; lp[c*4+1] = v.y; lp[c*4+2] = v.z; lp[c*4+3] = v.w;
            }
            float gp[PVN * 3];
#pragma unroll
            for (int pp = 0; pp < PVN; pp++) {
                float lx = lp[pp*3+0], ly = lp[pp*3+1], lz = lp[pp*3+2];
                gp[pp*3+0] = R[0]*lx + R[1]*ly + R[2]*lz + tr[0];
                gp[pp*3+1] = R[3]*lx + R[4]*ly + R[5]*lz + tr[1];
                gp[pp*3+2] = R[6]*lx + R[7]*ly + R[8]*lz + tr[2];
            }
            float4* dst = reinterpret_cast<float4*>(g_vpP + ((long)rp * HPV3 + h * PVN * 3));
#pragma unroll
            for (int c = 0; c < 6; c++)
                dst[c] = make_float4(gp[c*4+0], gp[c*4+1], gp[c*4+2], gp[c*4+3]);
        }
        return;
    }
    int i4 = i3 - POOLPT;
    if (i4 >= QPT) return;
    // q point transform (pooled frame)
    int h = i4 % HH;
    int rp = i4 / HH;
    float R[9], tr[3];
#pragma unroll
    for (int r = 0; r < 9; r++) R[r] = g_rP[rp * 9 + r];
#pragma unroll
    for (int r = 0; r < 3; r++) tr[r] = g_tP[rp * 3 + r];
    float lp[PQN * 3];
    float4* qp4 = reinterpret_cast<float4*>(g_qp + ((long)rp * HPQ3 + h * PQN * 3));
#pragma unroll
    for (int c = 0; c < 3; c++) {
        float4 v = qp4[c];
        lp[c*4+0] = v.x; lp[c*4+1] = v.y; lp[c*4+2] = v.z; lp[c*4+3] = v.w;
    }
    float gp[PQN * 3];
#pragma unroll
    for (int p = 0; p < PQN; p++) {
        float lx = lp[p*3+0], ly = lp[p*3+1], lz = lp[p*3+2];
        gp[p*3+0] = R[0]*lx + R[1]*ly + R[2]*lz + tr[0];
        gp[p*3+1] = R[3]*lx + R[4]*ly + R[5]*lz + tr[1];
        gp[p*3+2] = R[6]*lx + R[7]*ly + R[8]*lz + tr[2];
    }
#pragma unroll
    for (int c = 0; c < 3; c++)
        qp4[c] = make_float4(gp[c*4+0], gp[c*4+1], gp[c*4+2], gp[c*4+3]);
}

// ---------------------------------------------------------------------------
// Split-KV attention. Keys indexed from raw (j<NPAD) or pooled (j>=NPAD)
// arrays — no expanded intermediate. ulonglong2 smem loads + f32x2 FMA.
// grid (B*H, PROW/64, ATTS=4), 64 threads.
// ---------------------------------------------------------------------------
#define TJ 32
#define ATH 64
__global__ void attn_split_kernel(const float* __restrict__ gamma) {
    int bh = blockIdx.x;
    int b = bh / HH, h = bh % HH;
    int i = blockIdx.y * ATH + threadIdx.x;
    int sp = blockIdx.z;
    int tid = threadIdx.x;

    int j_begin = sp * ACHUNK;
    int j_end = j_begin + ACHUNK;
    if (j_end > TT) j_end = TT;

    __shared__ __align__(16) float k_s [TJ][CC];
    __shared__ __align__(16) float v_s [TJ][CC];
    __shared__ __align__(16) float kg_s[TJ][PQN * 3];
    __shared__ __align__(16) float vg_s[TJ][PVN * 3];
    __shared__ float sk_s[TJ];

    int qrow = b * PROW + i;
    u64 q2[CC / 2], qg2[PQN * 3 / 2];
    {
        const u64* q64 = reinterpret_cast<const u64*>(g_q + (long)qrow * HC + h * CC);
#pragma unroll
        for (int c = 0; c < CC / 2; c++) q2[c] = q64[c];
        const u64* g64 = reinterpret_cast<const u64*>(g_qp + (long)qrow * HPQ3 + h * PQN * 3);
#pragma unroll
        for (int c = 0; c < PQN * 3 / 2; c++) qg2[c] = g64[c];
    }
    float sq;
    {
        u64 a = 0ULL;
#pragma unroll
        for (int c = 0; c < PQN * 3 / 2; c++) fma2(a, qg2[c], qg2[c]);
        float lo, hi; unpack2(a, lo, hi);
        sq = lo + hi;
    }

    float gm = gamma[h];
    float gcoef = logf(1.f + __expf(gm)) * WC_HALF;

    float mrun = -1e30f, lrun = 0.f;
    u64 ao2[CC / 2], ag2[PVN * 3 / 2];
#pragma unroll
    for (int c = 0; c < CC / 2; c++) ao2[c] = 0ULL;
#pragma unroll
    for (int x = 0; x < PVN * 3 / 2; x++) ag2[x] = 0ULL;

    for (int j0 = j_begin; j0 < j_end; j0 += TJ) {
        __syncthreads();
        for (int x = tid; x < TJ * 4; x += ATH) {
            int j = x >> 2, c4 = x & 3;
            int jj = j0 + j;
            float4 v = make_float4(0.f, 0.f, 0.f, 0.f);
            if (jj < NPAD)
                v = reinterpret_cast<const float4*>(g_k0 + ((long)(b * NN + clampsrc(jj)) * HC + h * CC))[c4];
            else if (jj < TT)
                v = reinterpret_cast<const float4*>(g_kP + ((long)(b * PROW + (jj - NPAD)) * HC + h * CC))[c4];
            reinterpret_cast<float4*>(&k_s[j][0])[c4] = v;
        }
        for (int x = tid; x < TJ * 4; x += ATH) {
            int j = x >> 2, c4 = x & 3;
            int jj = j0 + j;
            float4 v = make_float4(0.f, 0.f, 0.f, 0.f);
            if (jj < NPAD)
                v = reinterpret_cast<const float4*>(g_v0 + ((long)(b * NN + clampsrc(jj)) * HC + h * CC))[c4];
            else if (jj < TT)
                v = reinterpret_cast<const float4*>(g_vP + ((long)(b * PROW + (jj - NPAD)) * HC + h * CC))[c4];
            reinterpret_cast<float4*>(&v_s[j][0])[c4] = v;
        }
        for (int x = tid; x < TJ * 3; x += ATH) {
            int j = x / 3, c4 = x % 3;
            int jj = j0 + j;
            float4 v = make_float4(0.f, 0.f, 0.f, 0.f);
            if (jj < NPAD)
                v = reinterpret_cast<const float4*>(g_kpT + ((long)(b * NN + clampsrc(jj)) * HPQ3 + h * PQN * 3))[c4];
            else if (jj < TT)
                v = reinterpret_cast<const float4*>(g_kpP + ((long)(b * PROW + (jj - NPAD)) * HPQ3 + h * PQN * 3))[c4];
            reinterpret_cast<float4*>(&kg_s[j][0])[c4] = v;
        }
        for (int x = tid; x < TJ * 6; x += ATH) {
            int j = x / 6, c4 = x % 6;
            int jj = j0 + j;
            float4 v = make_float4(0.f, 0.f, 0.f, 0.f);
            if (jj < NPAD)
                v = reinterpret_cast<const float4*>(g_vpT + ((long)(b * NN + clampsrc(jj)) * HPV3 + h * PVN * 3))[c4];
            else if (jj < TT)
                v = reinterpret_cast<const float4*>(g_vpP + ((long)(b * PROW + (jj - NPAD)) * HPV3 + h * PVN * 3))[c4];
            reinterpret_cast<float4*>(&vg_s[j][0])[c4] = v;
        }
        for (int x = tid; x < TJ; x += ATH) {
            int jj = j0 + x;
            float v = 0.f;
            if (jj < NPAD)
                v = g_skR[((long)(b * NN + clampsrc(jj))) * HH + h];
            else if (jj < TT)
                v = g_skP[((long)(b * PROW + (jj - NPAD))) * HH + h];
            sk_s[x] = v;
        }
        __syncthreads();

        int nv = j_end - j0;
        if (nv > TJ) nv = TJ;

        float logit[TJ];
        float tmax = -1e30f;
#pragma unroll
        for (int jj = 0; jj < TJ; jj++) {
            u64 a1 = 0ULL;
            const ulonglong2* k128 = reinterpret_cast<const ulonglong2*>(&k_s[jj][0]);
#pragma unroll
            for (int c = 0; c < CC / 4; c++) {
                ulonglong2 kv = k128[c];
                fma2(a1, q2[2*c], kv.x);
                fma2(a1, q2[2*c+1], kv.y);
            }
            u64 a2 = 0ULL;
            {
                // 12 floats = 1 ulonglong2 + 1 u64
                const ulonglong2* kg128 = reinterpret_cast<const ulonglong2*>(&kg_s[jj][0]);
                ulonglong2 kv0 = kg128[0];
                fma2(a2, qg2[0], kv0.x);
                fma2(a2, qg2[1], kv0.y);
                ulonglong2 kv1 = kg128[1];
                fma2(a2, qg2[2], kv1.x);
                fma2(a2, qg2[3], kv1.y);
                ulonglong2 kv2 = kg128[2];
                fma2(a2, qg2[4], kv2.x);
                fma2(a2, qg2[5], kv2.y);
            }
            float l1, h1, l2, h2;
            unpack2(a1, l1, h1);
            unpack2(a2, l2, h2);
            float qk = l1 + h1;
            float dt = l2 + h2;
            float d2 = sq + sk_s[jj] - 2.f * dt;
            float lg = C1 * qk - gcoef * d2;
            logit[jj] = (jj < nv) ? lg : -1e30f;
            tmax = fmaxf(tmax, logit[jj]);
        }
        float mn = fmaxf(mrun, tmax);
        float corr = __expf(mrun - mn);
        lrun *= corr;
        u64 corr2 = pack2(corr, corr);
#pragma unroll
        for (int c = 0; c < CC / 2; c++) mul2ip(ao2[c], corr2);
#pragma unroll
        for (int x = 0; x < PVN * 3 / 2; x++) mul2ip(ag2[x], corr2);
#pragma unroll
        for (int jj = 0; jj < TJ; jj++) {
            float e = __expf(logit[jj] - mn);
            lrun += e;
            u64 ee = pack2(e, e);
            const ulonglong2* v128 = reinterpret_cast<const ulonglong2*>(&v_s[jj][0]);
#pragma unroll
            for (int c = 0; c < CC / 4; c++) {
                ulonglong2 vv = v128[c];
                fma2(ao2[2*c], ee, vv.x);
                fma2(ao2[2*c+1], ee, vv.y);
            }
            const ulonglong2* g128 = reinterpret_cast<const ulonglong2*>(&vg_s[jj][0]);
#pragma unroll
            for (int c = 0; c < PVN * 3 / 4; c++) {
                ulonglong2 vv = g128[c];
                fma2(ag2[2*c], ee, vv.x);
                fma2(ag2[2*c+1], ee, vv.y);
            }
        }
        mrun = mn;
    }

    int p = (qrow * HH + h) * ATTS + sp;
    g_pm[p] = mrun;
    g_pl[p] = lrun;
#pragma unroll
    for (int c = 0; c < CC / 2; c++) {
        float lo, hi; unpack2(ao2[c], lo, hi);
        g_po[(long)p * CC + 2*c] = lo;
        g_po[(long)p * CC + 2*c + 1] = hi;
    }
#pragma unroll
    for (int x = 0; x < PVN * 3 / 2; x++) {
        float lo, hi; unpack2(ag2[x], lo, hi);
        g_pg[(long)p * (PVN * 3) + 2*x] = lo;
        g_pg[(long)p * (PVN * 3) + 2*x + 1] = hi;
    }
}

// ---------------------------------------------------------------------------
// Combine split partials + build oc rows. One thread per (b,i,h).
// ---------------------------------------------------------------------------
__global__ void combine_oc_kernel() {
    int idx = blockIdx.x * blockDim.x + threadIdx.x;
    if (idx >= BB * PROW * HH) return;
    int h = idx % HH;
    int row = idx / HH;          // b*PROW + i
    int p0 = idx * ATTS;

    float m = -1e30f;
#pragma unroll
    for (int s = 0; s < ATTS; s++) m = fmaxf(m, g_pm[p0 + s]);
    float L = 0.f;
    float o[CC], g[PVN * 3];
#pragma unroll
    for (int c = 0; c < CC; c++) o[c] = 0.f;
#pragma unroll
    for (int x = 0; x < PVN * 3; x++) g[x] = 0.f;
#pragma unroll
    for (int s = 0; s < ATTS; s++) {
        float w = __expf(g_pm[p0 + s] - m);
        L += g_pl[p0 + s] * w;
        const float* po = g_po + (long)(p0 + s) * CC;
        const float* pg = g_pg + (long)(p0 + s) * (PVN * 3);
#pragma unroll
        for (int c = 0; c < CC; c++) o[c] += w * po[c];
#pragma unroll
        for (int x = 0; x < PVN * 3; x++) g[x] += w * pg[x];
    }
    float inv = 1.f / L;
#pragma unroll
    for (int c = 0; c < CC; c++) o[c] *= inv;
#pragma unroll
    for (int x = 0; x < PVN * 3; x++) g[x] *= inv;

    float R[9], tr[3];
#pragma unroll
    for (int r = 0; r < 9; r++) R[r] = g_rP[row * 9 + r];
#pragma unroll
    for (int r = 0; r < 3; r++) tr[r] = g_tP[row * 3 + r];

#pragma unroll
    for (int c = 0; c < CC; c++)
        g_oc[(long)row * OCW + h * CC + c] = o[c];

#pragma unroll
    for (int pp = 0; pp < PVN; pp++) {
        float gx = g[pp * 3 + 0] - tr[0];
        float gy = g[pp * 3 + 1] - tr[1];
        float gz = g[pp * 3 + 2] - tr[2];
        float lx = R[0] * gx + R[3] * gy + R[6] * gz;
        float ly = R[1] * gx + R[4] * gy + R[7] * gz;
        float lz = R[2] * gx + R[5] * gy + R[8] * gz;
        g_oc[(long)row * OCW + HC + h * PVN * 3 + pp * 3 + 0] = lx;
        g_oc[(long)row * OCW + HC + h * PVN * 3 + pp * 3 + 1] = ly;
        g_oc[(long)row * OCW + HC + h * PVN * 3 + pp * 3 + 2] = lz;
        g_oc[(long)row * OCW + HC + HPV3 + h * PVN + pp] =
            sqrtf(lx * lx + ly * ly + lz * lz + 1e-8f);
    }
}

// ---------------------------------------------------------------------------
// Finalize: warp per row.
// ---------------------------------------------------------------------------
__global__ void finalize_kernel(const float* __restrict__ bupd,
                                float* __restrict__ out) {
    int gw = (blockIdx.x * blockDim.x + threadIdx.x) >> 5;
    int lane = threadIdx.x & 31;
    if (gw >= BB * PROW) return;
    int row = gw;

    float acc[6] = {0.f, 0.f, 0.f, 0.f, 0.f, 0.f};
    const float* ocr = g_oc + (long)row * OCW;
    for (int k = lane; k < OCW; k += 32) {
        float v = ocr[k];
#pragma unroll
        for (int j = 0; j < 6; j++) acc[j] += v * g_wfold[j * OCW + k];
    }
#pragma unroll
    for (int off = 16; off > 0; off >>= 1)
#pragma unroll
        for (int j = 0; j < 6; j++)
            acc[j] += __shfl_down_sync(0xffffffffu, acc[j], off);
    if (lane != 0) return;

    float u[6];
#pragma unroll
    for (int j = 0; j < 6; j++) u[j] = acc[j] + bupd[j];

    float bq = u[0], cq = u[1], dq = u[2];
    float ninv = rsqrtf(1.f + bq * bq + cq * cq + dq * dq);
    float w = ninv, x = bq * ninv, y = cq * ninv, z = dq * ninv;
    float Ru[9];
    Ru[0] = 1.f - 2.f * (y * y + z * z); Ru[1] = 2.f * (x * y - w * z); Ru[2] = 2.f * (x * z + w * y);
    Ru[3] = 2.f * (x * y + w * z); Ru[4] = 1.f - 2.f * (x * x + z * z); Ru[5] = 2.f * (y * z - w * x);
    Ru[6] = 2.f * (x * z - w * y); Ru[7] = 2.f * (y * z + w * x); Ru[8] = 1.f - 2.f * (x * x + y * y);

    float R[9];
#pragma unroll
    for (int r = 0; r < 9; r++) R[r] = g_rP[row * 9 + r];

    float Rn[9];
#pragma unroll
    for (int r = 0; r < 3; r++)
#pragma unroll
        for (int c = 0; c < 3; c++) {
            float a = 0.f;
#pragma unroll
            for (int k = 0; k < 3; k++) a += R[r * 3 + k] * Ru[k * 3 + c];
            Rn[r * 3 + c] = a;
        }

    out[row * 3 + 0] = R[0] * u[3] + R[1] * u[4] + R[2] * u[5] + g_tP[row * 3 + 0];
    out[row * 3 + 1] = R[3] * u[3] + R[4] * u[4] + R[5] * u[5] + g_tP[row * 3 + 1];
    out[row * 3 + 2] = R[6] * u[3] + R[7] * u[4] + R[8] * u[5] + g_tP[row * 3 + 2];
    float* rout = out + BB * PROW * 3;
#pragma unroll
    for (int r = 0; r < 9; r++) rout[row * 9 + r] = Rn[r];
}

// ---------------------------------------------------------------------------
extern "C" void kernel_launch(void* const* d_in, const int* in_sizes, int n_in,
                              void* d_out, int out_size) {
    const float* trans = (const float*)d_in[0];
    const float* rots  = (const float*)d_in[1];
    const float* s     = (const float*)d_in[2];
    const float* wq    = (const float*)d_in[3];
    const float* wk    = (const float*)d_in[4];
    const float* wv    = (const float*)d_in[5];
    const float* wqp   = (const float*)d_in[6];
    const float* wkp   = (const float*)d_in[7];
    const float* wvp   = (const float*)d_in[8];
    const float* gamma = (const float*)d_in[9];
    const float* wout  = (const float*)d_in[10];
    const float* wupd  = (const float*)d_in[11];
    const float* bupd  = (const float*)d_in[12];
    float* out = (float*)d_out;

    float *p_s_pool, *p_k0, *p_v0, *p_kp0, *p_vp0, *p_q, *p_qp;
    cudaGetSymbolAddress((void**)&p_s_pool, g_s_pool);
    cudaGetSymbolAddress((void**)&p_k0, g_k0);
    cudaGetSymbolAddress((void**)&p_v0, g_v0);
    cudaGetSymbolAddress((void**)&p_kp0, g_kp0);
    cudaGetSymbolAddress((void**)&p_vp0, g_vp0);
    cudaGetSymbolAddress((void**)&p_q, g_q);
    cudaGetSymbolAddress((void**)&p_qp, g_qp);

    // 1. prep (pooled s + pooled t/r only)
    prep_all_kernel<<<(SP_TOT + TRP_TOT + 255) / 256, 256>>>(s, trans, rots);

    // 2. projection GEMMs
    TaskPack P;
    int Mraw = BB * NN;
    int Mpool = BB * PROW;
    auto setTask = [&](int ti, const float* A, const float* B, float* C,
                       int M, int N, int K) {
        P.t[ti].A = A; P.t[ti].B = B; P.t[ti].C = C;
        P.t[ti].M = M; P.t[ti].N = N; P.t[ti].K = K;
        P.t[ti].gx = (N + GBN - 1) / GBN;
    };
    setTask(0, s, wk,  p_k0,  Mraw, HC,   CSD);
    setTask(1, s, wv,  p_v0,  Mraw, HC,   CSD);
    setTask(2, s, wkp, p_kp0, Mraw, HPQ3, CSD);
    setTask(3, s, wvp, p_vp0, Mraw, HPV3, CSD);
    setTask(4, p_s_pool, wq,  p_q,  Mpool, HC,   CSD);
    setTask(5, p_s_pool, wqp, p_qp, Mpool, HPQ3, CSD);
    P.ofs[0] = 0;
    for (int ti = 0; ti < NTASK; ti++) {
        int gy = (P.t[ti].M + GBM - 1) / GBM;
        P.ofs[ti + 1] = P.ofs[ti] + P.t[ti].gx * gy;
    }
    mgemm_kernel<<<P.ofs[NTASK], 256>>>(P);

    // 3. weight fold
    fold_w_kernel<<<(OCW * 32 + 255) / 256, 256>>>(wout, wupd);

    // 4. transforms (raw rotate + pooled avg/rotate + q rotate)
    transform_kernel<<<(XF_TOT + 255) / 256, 256>>>(trans, rots);

    // 5. split-KV attention (raw/pooled indexed, f32x2)
    attn_split_kernel<<<dim3(BB * HH, PROW / ATH, ATTS), ATH>>>(gamma);

    // 6. combine + build oc
    combine_oc_kernel<<<(BB * PROW * HH + 255) / 256, 256>>>();

    // 7. finalize
    finalize_kernel<<<(BB * PROW * 32 + 255) / 256, 256>>>(bupd, out);
}

// round 10
// speedup vs baseline: 1.4081x; 1.2001x over previous
#include <cuda_runtime.h>
#include <math.h>

// Problem constants
#define BB 2
#define NN 1024
#define CSD 384
#define HH 12
#define CC 16
#define PQN 4
#define PVN 8
#define NPAD 1026        // N + 2*PAD
#define PROW 512         // num_pool
#define TT 1538          // NPAD + PROW
#define HC 192           // H*C
#define HPQ3 144         // H*PQ*3
#define HPV3 288         // H*PV*3
#define OCW 576          // HC + HPV3 + H*PV
#define ATTS 4           // split-KV factor (proven)
#define ACHUNK ((TT + ATTS - 1) / ATTS)   // 385

#define C1 0.176776695f       // w_l * (1/sqrt(C))
#define WC_HALF 0.117851130f  // w_c/2

typedef unsigned long long u64;

// packed f32x2 helpers (Blackwell sm_100a+)
__device__ __forceinline__ void fma2(u64 &d, u64 a, u64 b) {
    asm("fma.rn.f32x2 %0, %1, %2, %0;" : "+l"(d) : "l"(a), "l"(b));
}
__device__ __forceinline__ void mul2ip(u64 &d, u64 a) {
    asm("mul.rn.f32x2 %0, %0, %1;" : "+l"(d) : "l"(a));
}
__device__ __forceinline__ u64 pack2(float lo, float hi) {
    u64 r; asm("mov.b64 %0, {%1, %2};" : "=l"(r) : "f"(lo), "f"(hi)); return r;
}
__device__ __forceinline__ void unpack2(u64 v, float &lo, float &hi) {
    asm("mov.b64 {%0, %1}, %2;" : "=f"(lo), "=f"(hi) : "l"(v));
}
__device__ __forceinline__ unsigned f2tf32(float v) {
    unsigned r; asm("cvt.rna.tf32.f32 %0, %1;" : "=r"(r) : "f"(v)); return r;
}

// Scratch (device globals)
__device__ float g_s_pool[BB*PROW*CSD];
// pooled-only frames
__device__ float g_tP[BB*PROW*3];
__device__ float g_rP[BB*PROW*9];
// raw-row projections (GEMM outputs)
__device__ float g_k0 [BB*NN*HC];
__device__ float g_v0 [BB*NN*HC];
__device__ float g_kp0[BB*NN*HPQ3];
__device__ float g_vp0[BB*NN*HPV3];
// transformed raw points + raw sk
__device__ float g_kpT[BB*NN*HPQ3];
__device__ float g_vpT[BB*NN*HPV3];
__device__ float g_skR[BB*NN*HH];
// pooled keys/values (averages) + transformed pooled points
__device__ float g_kP [BB*PROW*HC];
__device__ float g_vP [BB*PROW*HC];
__device__ float g_kpP[BB*PROW*HPQ3];
__device__ float g_vpP[BB*PROW*HPV3];
__device__ float g_skP[BB*PROW*HH];
// queries (pooled rows)
__device__ float g_q  [BB*PROW*HC];
__device__ float g_qp [BB*PROW*HPQ3];
__device__ float g_oc [BB*PROW*OCW];
__device__ float g_wfold[6*OCW];

#define NPART (BB*PROW*HH*ATTS)
__device__ float g_pm[NPART];
__device__ float g_pl[NPART];
__device__ float g_po[NPART*CC];
__device__ float g_pg[NPART*PVN*3];

__device__ __forceinline__ int clampsrc(int e) {
    int v = e - 1;
    return v < 0 ? 0 : (v > NN - 1 ? NN - 1 : v);
}

// ---------------------------------------------------------------------------
// Prep: pooled s rows + pooled-only t/r
// ---------------------------------------------------------------------------
#define SP_TOT (BB*PROW*CSD)
#define TRP_TOT (BB*PROW*12)
__global__ void prep_all_kernel(const float* __restrict__ s,
                                const float* __restrict__ trans,
                                const float* __restrict__ rots) {
    int idx = blockIdx.x * blockDim.x + threadIdx.x;
    if (idx < SP_TOT) {
        int c = idx % CSD;
        int bp = idx / CSD;
        int p = bp % PROW;
        int b = bp / PROW;
        g_s_pool[idx] = (s[(b * NN + clampsrc(2 * p    )) * CSD + c]
                       + s[(b * NN + clampsrc(2 * p + 1)) * CSD + c]
                       + s[(b * NN + clampsrc(2 * p + 2)) * CSD + c]) * (1.f / 3.f);
        return;
    }
    int k = idx - SP_TOT;
    if (k >= TRP_TOT) return;
    int d = k % 12;
    int bp = k / 12;
    int p = bp % PROW;
    int b = bp / PROW;
    int r0 = clampsrc(2 * p), r1 = clampsrc(2 * p + 1), r2 = clampsrc(2 * p + 2);
    if (d < 3) {
        g_tP[bp * 3 + d] = (trans[(b * NN + r0) * 3 + d]
                          + trans[(b * NN + r1) * 3 + d]
                          + trans[(b * NN + r2) * 3 + d]) * (1.f / 3.f);
    } else {
        int r = d - 3;
        g_rP[bp * 9 + r] = (rots[(b * NN + r0) * 9 + r]
                          + rots[(b * NN + r1) * 9 + r]
                          + rots[(b * NN + r2) * 9 + r]) * (1.f / 3.f);
    }
}

// ---------------------------------------------------------------------------
// Fused multi-task GEMM on TENSOR CORES (tf32 mma.sync m16n8k8).
// Tile 64x64, BK=16, 256 threads = 8 warps in 4(M)x2(N) grid of 16x32 regions.
// Inputs converted to tf32 once in the global->smem stage.
// ---------------------------------------------------------------------------
#define NTASK 6
struct GemmTask {
    const float* A;
    const float* B;
    float* C;
    int M, N, K, gx;
};
struct TaskPack {
    GemmTask t[NTASK];
    int ofs[NTASK + 1];
};

#define GBM 64
#define GBN 64
#define GBK 16
__global__ void mgemm_kernel(TaskPack P) {
    int bid = blockIdx.x;
    int ti = 0;
#pragma unroll
    for (int x = 0; x < NTASK - 1; x++)
        if (bid >= P.ofs[x + 1]) ti = x + 1;
    GemmTask tk = P.t[ti];
    int lb = bid - P.ofs[ti];
    int bx = lb % tk.gx, by = lb / tk.gx;

    __shared__ unsigned As[GBM][GBK + 1];   // [64][17] padded
    __shared__ unsigned Bs[GBK][GBN + 8];   // [16][72] padded

    int tid = threadIdx.x;
    int warp = tid >> 5, lane = tid & 31;
    int gid = lane >> 2, tig = lane & 3;
    int wm = warp & 3;          // 0..3 -> M strip of 16
    int wn = warp >> 2;         // 0..1 -> N half of 32
    int row0 = by * GBM;
    int col0 = bx * GBN;
    const float* A = tk.A;
    const float* Bm = tk.B;
    int M = tk.M, Nn = tk.N, K = tk.K;

    float d[4][4];              // [ntile][c0..c3]
#pragma unroll
    for (int t = 0; t < 4; t++)
#pragma unroll
        for (int c = 0; c < 4; c++) d[t][c] = 0.f;

    for (int k0 = 0; k0 < K; k0 += GBK) {
        // load + convert A tile (64x16)
#pragma unroll
        for (int x = 0; x < 4; x++) {
            int li = tid + x * 256;
            int m = li >> 4, kk = li & 15;
            int gm = row0 + m;
            float v = (gm < M) ? A[(long)gm * K + k0 + kk] : 0.f;
            As[m][kk] = f2tf32(v);
        }
        // load + convert B tile (16x64)
#pragma unroll
        for (int x = 0; x < 4; x++) {
            int li = tid + x * 256;
            int kk = li >> 6, n = li & 63;
            int gn = col0 + n;
            float v = (gn < Nn) ? Bm[(long)(k0 + kk) * Nn + gn] : 0.f;
            Bs[kk][n] = f2tf32(v);
        }
        __syncthreads();

#pragma unroll
        for (int ks = 0; ks < 2; ks++) {
            int kb = ks * 8;
            int ra = wm * 16 + gid;
            unsigned a0 = As[ra][kb + tig];
            unsigned a1 = As[ra + 8][kb + tig];
            unsigned a2 = As[ra][kb + tig + 4];
            unsigned a3 = As[ra + 8][kb + tig + 4];
#pragma unroll
            for (int t = 0; t < 4; t++) {
                int nb = wn * 32 + t * 8;
                unsigned b0 = Bs[kb + tig][nb + gid];
                unsigned b1 = Bs[kb + tig + 4][nb + gid];
                asm volatile(
                    "mma.sync.aligned.m16n8k8.row.col.f32.tf32.tf32.f32 "
                    "{%0,%1,%2,%3}, {%4,%5,%6,%7}, {%8,%9}, {%0,%1,%2,%3};"
                    : "+f"(d[t][0]), "+f"(d[t][1]), "+f"(d[t][2]), "+f"(d[t][3])
                    : "r"(a0), "r"(a1), "r"(a2), "r"(a3), "r"(b0), "r"(b1));
            }
        }
        __syncthreads();
    }

    // store (C fragment layout: c0=(gid,2tig), c1=(gid,2tig+1), c2=(gid+8,..))
#pragma unroll
    for (int t = 0; t < 4; t++) {
        int gn0 = col0 + wn * 32 + t * 8 + tig * 2;
        int gm0 = row0 + wm * 16 + gid;
        if (gm0 < M) {
            if (gn0 < Nn)     tk.C[(long)gm0 * Nn + gn0]     = d[t][0];
            if (gn0 + 1 < Nn) tk.C[(long)gm0 * Nn + gn0 + 1] = d[t][1];
        }
        int gm1 = gm0 + 8;
        if (gm1 < M) {
            if (gn0 < Nn)     tk.C[(long)gm1 * Nn + gn0]     = d[t][2];
            if (gn0 + 1 < Nn) tk.C[(long)gm1 * Nn + gn0 + 1] = d[t][3];
        }
    }
}

// ---------------------------------------------------------------------------
// Weight fold: warp per OCW-row.
// ---------------------------------------------------------------------------
__global__ void fold_w_kernel(const float* __restrict__ wout,
                              const float* __restrict__ wupd) {
    int gw = (blockIdx.x * blockDim.x + threadIdx.x) >> 5;
    int lane = threadIdx.x & 31;
    if (gw >= OCW) return;
    const float* wr = wout + (long)gw * CSD;
    float acc[6] = {0, 0, 0, 0, 0, 0};
    for (int m = lane; m < CSD; m += 32) {
        float w = wr[m];
#pragma unroll
        for (int j = 0; j < 6; j++) acc[j] += w * __ldg(&wupd[m * 6 + j]);
    }
#pragma unroll
    for (int off = 16; off > 0; off >>= 1)
#pragma unroll
        for (int j = 0; j < 6; j++)
            acc[j] += __shfl_down_sync(0xffffffffu, acc[j], off);
    if (lane == 0) {
#pragma unroll
        for (int j = 0; j < 6; j++) g_wfold[j * OCW + gw] = acc[j];
    }
}

// ---------------------------------------------------------------------------
// Transform kernel (round-9 proven), 4 ranges.
// ---------------------------------------------------------------------------
#define RAWPT (BB*NN*HH)
#define POOLKV (BB*PROW*(HC/4)*2)
#define POOLPT (BB*PROW*HH)
#define QPT (BB*PROW*HH)
#define XF_TOT (RAWPT + POOLKV + POOLPT + QPT)

__device__ __forceinline__ float4 avg3f4(float4 a, float4 b, float4 c) {
    return make_float4((a.x + b.x + c.x) * (1.f / 3.f),
                       (a.y + b.y + c.y) * (1.f / 3.f),
                       (a.z + b.z + c.z) * (1.f / 3.f),
                       (a.w + b.w + c.w) * (1.f / 3.f));
}

__global__ void transform_kernel(const float* __restrict__ trans,
                                 const float* __restrict__ rots) {
    int idx = blockIdx.x * blockDim.x + threadIdx.x;
    if (idx < RAWPT) {
        int h = idx % HH;
        int rn = idx / HH;
        float R[9], tr[3];
#pragma unroll
        for (int r = 0; r < 9; r++) R[r] = rots[rn * 9 + r];
#pragma unroll
        for (int r = 0; r < 3; r++) tr[r] = trans[rn * 3 + r];

        {
            const float4* src = reinterpret_cast<const float4*>(g_kp0 + ((long)rn * HPQ3 + h * PQN * 3));
            float lp[PQN * 3];
#pragma unroll
            for (int c = 0; c < 3; c++) {
                float4 v = src[c];
                lp[c*4+0] = v.x; lp[c*4+1] = v.y; lp[c*4+2] = v.z; lp[c*4+3] = v.w;
            }
            float sk = 0.f;
            float gp[PQN * 3];
#pragma unroll
            for (int p = 0; p < PQN; p++) {
                float lx = lp[p*3+0], ly = lp[p*3+1], lz = lp[p*3+2];
                float gx = R[0]*lx + R[1]*ly + R[2]*lz + tr[0];
                float gy = R[3]*lx + R[4]*ly + R[5]*lz + tr[1];
                float gz = R[6]*lx + R[7]*ly + R[8]*lz + tr[2];
                gp[p*3+0] = gx; gp[p*3+1] = gy; gp[p*3+2] = gz;
                sk += gx*gx + gy*gy + gz*gz;
            }
            g_skR[rn * HH + h] = sk;
            float4* dst = reinterpret_cast<float4*>(g_kpT + ((long)rn * HPQ3 + h * PQN * 3));
#pragma unroll
            for (int c = 0; c < 3; c++)
                dst[c] = make_float4(gp[c*4+0], gp[c*4+1], gp[c*4+2], gp[c*4+3]);
        }
        {
            const float4* src = reinterpret_cast<const float4*>(g_vp0 + ((long)rn * HPV3 + h * PVN * 3));
            float lp[PVN * 3];
#pragma unroll
            for (int c = 0; c < 6; c++) {
                float4 v = src[c];
                lp[c*4+0] = v.x; lp[c*4+1] = v.y; lp[c*4+2] = v.z; lp[c*4+3] = v.w;
            }
            float gp[PVN * 3];
#pragma unroll
            for (int p = 0; p < PVN; p++) {
                float lx = lp[p*3+0], ly = lp[p*3+1], lz = lp[p*3+2];
                gp[p*3+0] = R[0]*lx + R[1]*ly + R[2]*lz + tr[0];
                gp[p*3+1] = R[3]*lx + R[4]*ly + R[5]*lz + tr[1];
                gp[p*3+2] = R[6]*lx + R[7]*ly + R[8]*lz + tr[2];
            }
            float4* dst = reinterpret_cast<float4*>(g_vpT + ((long)rn * HPV3 + h * PVN * 3));
#pragma unroll
            for (int c = 0; c < 6; c++)
                dst[c] = make_float4(gp[c*4+0], gp[c*4+1], gp[c*4+2], gp[c*4+3]);
        }
        return;
    }
    int i2 = idx - RAWPT;
    if (i2 < POOLKV) {
        int c = i2 % (HC / 4);
        int rest = i2 / (HC / 4);
        int rp = rest % (BB * PROW);
        int sel = rest / (BB * PROW);
        int p = rp % PROW;
        int b = rp / PROW;
        int r0 = clampsrc(2 * p), r1 = clampsrc(2 * p + 1), r2 = clampsrc(2 * p + 2);
        const float* srcbase = sel ? g_v0 : g_k0;
        float* dstbase = sel ? g_vP : g_kP;
        float4 a = reinterpret_cast<const float4*>(srcbase + ((long)(b * NN + r0) * HC))[c];
        float4 bb = reinterpret_cast<const float4*>(srcbase + ((long)(b * NN + r1) * HC))[c];
        float4 cc = reinterpret_cast<const float4*>(srcbase + ((long)(b * NN + r2) * HC))[c];
        reinterpret_cast<float4*>(dstbase + ((long)rp * HC))[c] = avg3f4(a, bb, cc);
        return;
    }
    int i3 = i2 - POOLKV;
    if (i3 < POOLPT) {
        int h = i3 % HH;
        int rp = i3 / HH;
        int p = rp % PROW;
        int b = rp / PROW;
        int r0 = clampsrc(2 * p), r1 = clampsrc(2 * p + 1), r2 = clampsrc(2 * p + 2);
        float R[9], tr[3];
#pragma unroll
        for (int r = 0; r < 9; r++) R[r] = g_rP[rp * 9 + r];
#pragma unroll
        for (int r = 0; r < 3; r++) tr[r] = g_tP[rp * 3 + r];

        {
            float lp[PQN * 3];
            const float4* a = reinterpret_cast<const float4*>(g_kp0 + ((long)(b * NN + r0) * HPQ3 + h * PQN * 3));
            const float4* bb = reinterpret_cast<const float4*>(g_kp0 + ((long)(b * NN + r1) * HPQ3 + h * PQN * 3));
            const float4* cc = reinterpret_cast<const float4*>(g_kp0 + ((long)(b * NN + r2) * HPQ3 + h * PQN * 3));
#pragma unroll
            for (int c = 0; c < 3; c++) {
                float4 v = avg3f4(a[c], bb[c], cc[c]);
                lp[c*4+0] = v.x; lp[c*4+1] = v.y; lp[c*4+2] = v.z; lp[c*4+3] = v.w;
            }
            float sk = 0.f;
            float gp[PQN * 3];
#pragma unroll
            for (int pp = 0; pp < PQN; pp++) {
                float lx = lp[pp*3+0], ly = lp[pp*3+1], lz = lp[pp*3+2];
                float gx = R[0]*lx + R[1]*ly + R[2]*lz + tr[0];
                float gy = R[3]*lx + R[4]*ly + R[5]*lz + tr[1];
                float gz = R[6]*lx + R[7]*ly + R[8]*lz + tr[2];
                gp[pp*3+0] = gx; gp[pp*3+1] = gy; gp[pp*3+2] = gz;
                sk += gx*gx + gy*gy + gz*gz;
            }
            g_skP[rp * HH + h] = sk;
            float4* dst = reinterpret_cast<float4*>(g_kpP + ((long)rp * HPQ3 + h * PQN * 3));
#pragma unroll
            for (int c = 0; c < 3; c++)
                dst[c] = make_float4(gp[c*4+0], gp[c*4+1], gp[c*4+2], gp[c*4+3]);
        }
        {
            float lp[PVN * 3];
            const float4* a = reinterpret_cast<const float4*>(g_vp0 + ((long)(b * NN + r0) * HPV3 + h * PVN * 3));
            const float4* bb = reinterpret_cast<const float4*>(g_vp0 + ((long)(b * NN + r1) * HPV3 + h * PVN * 3));
            const float4* cc = reinterpret_cast<const float4*>(g_vp0 + ((long)(b * NN + r2) * HPV3 + h * PVN * 3));
#pragma unroll
            for (int c = 0; c < 6; c++) {
                float4 v = avg3f4(a[c], bb[c], cc[c]);
                lp[c*4+0] = v.x; lp[c*4+1] = v.y; lp[c*4+2] = v.z; lp[c*4+3] = v.w;
            }
            float gp[PVN * 3];
#pragma unroll
            for (int pp = 0; pp < PVN; pp++) {
                float lx = lp[pp*3+0], ly = lp[pp*3+1], lz = lp[pp*3+2];
                gp[pp*3+0] = R[0]*lx + R[1]*ly + R[2]*lz + tr[0];
                gp[pp*3+1] = R[3]*lx + R[4]*ly + R[5]*lz + tr[1];
                gp[pp*3+2] = R[6]*lx + R[7]*ly + R[8]*lz + tr[2];
            }
            float4* dst = reinterpret_cast<float4*>(g_vpP + ((long)rp * HPV3 + h * PVN * 3));
#pragma unroll
            for (int c = 0; c < 6; c++)
                dst[c] = make_float4(gp[c*4+0], gp[c*4+1], gp[c*4+2], gp[c*4+3]);
        }
        return;
    }
    int i4 = i3 - POOLPT;
    if (i4 >= QPT) return;
    int h = i4 % HH;
    int rp = i4 / HH;
    float R[9], tr[3];
#pragma unroll
    for (int r = 0; r < 9; r++) R[r] = g_rP[rp * 9 + r];
#pragma unroll
    for (int r = 0; r < 3; r++) tr[r] = g_tP[rp * 3 + r];
    float lp[PQN * 3];
    float4* qp4 = reinterpret_cast<float4*>(g_qp + ((long)rp * HPQ3 + h * PQN * 3));
#pragma unroll
    for (int c = 0; c < 3; c++) {
        float4 v = qp4[c];
        lp[c*4+0] = v.x; lp[c*4+1] = v.y; lp[c*4+2] = v.z; lp[c*4+3] = v.w;
    }
    float gp[PQN * 3];
#pragma unroll
    for (int p = 0; p < PQN; p++) {
        float lx = lp[p*3+0], ly = lp[p*3+1], lz = lp[p*3+2];
        gp[p*3+0] = R[0]*lx + R[1]*ly + R[2]*lz + tr[0];
        gp[p*3+1] = R[3]*lx + R[4]*ly + R[5]*lz + tr[1];
        gp[p*3+2] = R[6]*lx + R[7]*ly + R[8]*lz + tr[2];
    }
#pragma unroll
    for (int c = 0; c < 3; c++)
        qp4[c] = make_float4(gp[c*4+0], gp[c*4+1], gp[c*4+2], gp[c*4+3]);
}

// ---------------------------------------------------------------------------
// Split-KV attention (round-9 proven). Keys indexed raw/pooled, f32x2 math.
// ---------------------------------------------------------------------------
#define TJ 32
#define ATH 64
__global__ void attn_split_kernel(const float* __restrict__ gamma) {
    int bh = blockIdx.x;
    int b = bh / HH, h = bh % HH;
    int i = blockIdx.y * ATH + threadIdx.x;
    int sp = blockIdx.z;
    int tid = threadIdx.x;

    int j_begin = sp * ACHUNK;
    int j_end = j_begin + ACHUNK;
    if (j_end > TT) j_end = TT;

    __shared__ __align__(16) float k_s [TJ][CC];
    __shared__ __align__(16) float v_s [TJ][CC];
    __shared__ __align__(16) float kg_s[TJ][PQN * 3];
    __shared__ __align__(16) float vg_s[TJ][PVN * 3];
    __shared__ float sk_s[TJ];

    int qrow = b * PROW + i;
    u64 q2[CC / 2], qg2[PQN * 3 / 2];
    {
        const u64* q64 = reinterpret_cast<const u64*>(g_q + (long)qrow * HC + h * CC);
#pragma unroll
        for (int c = 0; c < CC / 2; c++) q2[c] = q64[c];
        const u64* g64 = reinterpret_cast<const u64*>(g_qp + (long)qrow * HPQ3 + h * PQN * 3);
#pragma unroll
        for (int c = 0; c < PQN * 3 / 2; c++) qg2[c] = g64[c];
    }
    float sq;
    {
        u64 a = 0ULL;
#pragma unroll
        for (int c = 0; c < PQN * 3 / 2; c++) fma2(a, qg2[c], qg2[c]);
        float lo, hi; unpack2(a, lo, hi);
        sq = lo + hi;
    }

    float gm = gamma[h];
    float gcoef = logf(1.f + __expf(gm)) * WC_HALF;

    float mrun = -1e30f, lrun = 0.f;
    u64 ao2[CC / 2], ag2[PVN * 3 / 2];
#pragma unroll
    for (int c = 0; c < CC / 2; c++) ao2[c] = 0ULL;
#pragma unroll
    for (int x = 0; x < PVN * 3 / 2; x++) ag2[x] = 0ULL;

    for (int j0 = j_begin; j0 < j_end; j0 += TJ) {
        __syncthreads();
        for (int x = tid; x < TJ * 4; x += ATH) {
            int j = x >> 2, c4 = x & 3;
            int jj = j0 + j;
            float4 v = make_float4(0.f, 0.f, 0.f, 0.f);
            if (jj < NPAD)
                v = reinterpret_cast<const float4*>(g_k0 + ((long)(b * NN + clampsrc(jj)) * HC + h * CC))[c4];
            else if (jj < TT)
                v = reinterpret_cast<const float4*>(g_kP + ((long)(b * PROW + (jj - NPAD)) * HC + h * CC))[c4];
            reinterpret_cast<float4*>(&k_s[j][0])[c4] = v;
        }
        for (int x = tid; x < TJ * 4; x += ATH) {
            int j = x >> 2, c4 = x & 3;
            int jj = j0 + j;
            float4 v = make_float4(0.f, 0.f, 0.f, 0.f);
            if (jj < NPAD)
                v = reinterpret_cast<const float4*>(g_v0 + ((long)(b * NN + clampsrc(jj)) * HC + h * CC))[c4];
            else if (jj < TT)
                v = reinterpret_cast<const float4*>(g_vP + ((long)(b * PROW + (jj - NPAD)) * HC + h * CC))[c4];
            reinterpret_cast<float4*>(&v_s[j][0])[c4] = v;
        }
        for (int x = tid; x < TJ * 3; x += ATH) {
            int j = x / 3, c4 = x % 3;
            int jj = j0 + j;
            float4 v = make_float4(0.f, 0.f, 0.f, 0.f);
            if (jj < NPAD)
                v = reinterpret_cast<const float4*>(g_kpT + ((long)(b * NN + clampsrc(jj)) * HPQ3 + h * PQN * 3))[c4];
            else if (jj < TT)
                v = reinterpret_cast<const float4*>(g_kpP + ((long)(b * PROW + (jj - NPAD)) * HPQ3 + h * PQN * 3))[c4];
            reinterpret_cast<float4*>(&kg_s[j][0])[c4] = v;
        }
        for (int x = tid; x < TJ * 6; x += ATH) {
            int j = x / 6, c4 = x % 6;
            int jj = j0 + j;
            float4 v = make_float4(0.f, 0.f, 0.f, 0.f);
            if (jj < NPAD)
                v = reinterpret_cast<const float4*>(g_vpT + ((long)(b * NN + clampsrc(jj)) * HPV3 + h * PVN * 3))[c4];
            else if (jj < TT)
                v = reinterpret_cast<const float4*>(g_vpP + ((long)(b * PROW + (jj - NPAD)) * HPV3 + h * PVN * 3))[c4];
            reinterpret_cast<float4*>(&vg_s[j][0])[c4] = v;
        }
        for (int x = tid; x < TJ; x += ATH) {
            int jj = j0 + x;
            float v = 0.f;
            if (jj < NPAD)
                v = g_skR[((long)(b * NN + clampsrc(jj))) * HH + h];
            else if (jj < TT)
                v = g_skP[((long)(b * PROW + (jj - NPAD))) * HH + h];
            sk_s[x] = v;
        }
        __syncthreads();

        int nv = j_end - j0;
        if (nv > TJ) nv = TJ;

        float logit[TJ];
        float tmax = -1e30f;
#pragma unroll
        for (int jj = 0; jj < TJ; jj++) {
            u64 a1 = 0ULL;
            const ulonglong2* k128 = reinterpret_cast<const ulonglong2*>(&k_s[jj][0]);
#pragma unroll
            for (int c = 0; c < CC / 4; c++) {
                ulonglong2 kv = k128[c];
                fma2(a1, q2[2*c], kv.x);
                fma2(a1, q2[2*c+1], kv.y);
            }
            u64 a2 = 0ULL;
            {
                const ulonglong2* kg128 = reinterpret_cast<const ulonglong2*>(&kg_s[jj][0]);
                ulonglong2 kv0 = kg128[0];
                fma2(a2, qg2[0], kv0.x);
                fma2(a2, qg2[1], kv0.y);
                ulonglong2 kv1 = kg128[1];
                fma2(a2, qg2[2], kv1.x);
                fma2(a2, qg2[3], kv1.y);
                ulonglong2 kv2 = kg128[2];
                fma2(a2, qg2[4], kv2.x);
                fma2(a2, qg2[5], kv2.y);
            }
            float l1, h1, l2, h2;
            unpack2(a1, l1, h1);
            unpack2(a2, l2, h2);
            float qk = l1 + h1;
            float dt = l2 + h2;
            float d2 = sq + sk_s[jj] - 2.f * dt;
            float lg = C1 * qk - gcoef * d2;
            logit[jj] = (jj < nv) ? lg : -1e30f;
            tmax = fmaxf(tmax, logit[jj]);
        }
        float mn = fmaxf(mrun, tmax);
        float corr = __expf(mrun - mn);
        lrun *= corr;
        u64 corr2 = pack2(corr, corr);
#pragma unroll
        for (int c = 0; c < CC / 2; c++) mul2ip(ao2[c], corr2);
#pragma unroll
        for (int x = 0; x < PVN * 3 / 2; x++) mul2ip(ag2[x], corr2);
#pragma unroll
        for (int jj = 0; jj < TJ; jj++) {
            float e = __expf(logit[jj] - mn);
            lrun += e;
            u64 ee = pack2(e, e);
            const ulonglong2* v128 = reinterpret_cast<const ulonglong2*>(&v_s[jj][0]);
#pragma unroll
            for (int c = 0; c < CC / 4; c++) {
                ulonglong2 vv = v128[c];
                fma2(ao2[2*c], ee, vv.x);
                fma2(ao2[2*c+1], ee, vv.y);
            }
            const ulonglong2* g128 = reinterpret_cast<const ulonglong2*>(&vg_s[jj][0]);
#pragma unroll
            for (int c = 0; c < PVN * 3 / 4; c++) {
                ulonglong2 vv = g128[c];
                fma2(ag2[2*c], ee, vv.x);
                fma2(ag2[2*c+1], ee, vv.y);
            }
        }
        mrun = mn;
    }

    int p = (qrow * HH + h) * ATTS + sp;
    g_pm[p] = mrun;
    g_pl[p] = lrun;
#pragma unroll
    for (int c = 0; c < CC / 2; c++) {
        float lo, hi; unpack2(ao2[c], lo, hi);
        g_po[(long)p * CC + 2*c] = lo;
        g_po[(long)p * CC + 2*c + 1] = hi;
    }
#pragma unroll
    for (int x = 0; x < PVN * 3 / 2; x++) {
        float lo, hi; unpack2(ag2[x], lo, hi);
        g_pg[(long)p * (PVN * 3) + 2*x] = lo;
        g_pg[(long)p * (PVN * 3) + 2*x + 1] = hi;
    }
}

// ---------------------------------------------------------------------------
// Combine split partials + build oc rows. One thread per (b,i,h).
// ---------------------------------------------------------------------------
__global__ void combine_oc_kernel() {
    int idx = blockIdx.x * blockDim.x + threadIdx.x;
    if (idx >= BB * PROW * HH) return;
    int h = idx % HH;
    int row = idx / HH;
    int p0 = idx * ATTS;

    float m = -1e30f;
#pragma unroll
    for (int s = 0; s < ATTS; s++) m = fmaxf(m, g_pm[p0 + s]);
    float L = 0.f;
    float o[CC], g[PVN * 3];
#pragma unroll
    for (int c = 0; c < CC; c++) o[c] = 0.f;
#pragma unroll
    for (int x = 0; x < PVN * 3; x++) g[x] = 0.f;
#pragma unroll
    for (int s = 0; s < ATTS; s++) {
        float w = __expf(g_pm[p0 + s] - m);
        L += g_pl[p0 + s] * w;
        const float* po = g_po + (long)(p0 + s) * CC;
        const float* pg = g_pg + (long)(p0 + s) * (PVN * 3);
#pragma unroll
        for (int c = 0; c < CC; c++) o[c] += w * po[c];
#pragma unroll
        for (int x = 0; x < PVN * 3; x++) g[x] += w * pg[x];
    }
    float inv = 1.f / L;
#pragma unroll
    for (int c = 0; c < CC; c++) o[c] *= inv;
#pragma unroll
    for (int x = 0; x < PVN * 3; x++) g[x] *= inv;

    float R[9], tr[3];
#pragma unroll
    for (int r = 0; r < 9; r++) R[r] = g_rP[row * 9 + r];
#pragma unroll
    for (int r = 0; r < 3; r++) tr[r] = g_tP[row * 3 + r];

#pragma unroll
    for (int c = 0; c < CC; c++)
        g_oc[(long)row * OCW + h * CC + c] = o[c];

#pragma unroll
    for (int pp = 0; pp < PVN; pp++) {
        float gx = g[pp * 3 + 0] - tr[0];
        float gy = g[pp * 3 + 1] - tr[1];
        float gz = g[pp * 3 + 2] - tr[2];
        float lx = R[0] * gx + R[3] * gy + R[6] * gz;
        float ly = R[1] * gx + R[4] * gy + R[7] * gz;
        float lz = R[2] * gx + R[5] * gy + R[8] * gz;
        g_oc[(long)row * OCW + HC + h * PVN * 3 + pp * 3 + 0] = lx;
        g_oc[(long)row * OCW + HC + h * PVN * 3 + pp * 3 + 1] = ly;
        g_oc[(long)row * OCW + HC + h * PVN * 3 + pp * 3 + 2] = lz;
        g_oc[(long)row * OCW + HC + HPV3 + h * PVN + pp] =
            sqrtf(lx * lx + ly * ly + lz * lz + 1e-8f);
    }
}

// ---------------------------------------------------------------------------
// Finalize: warp per row.
// ---------------------------------------------------------------------------
__global__ void finalize_kernel(const float* __restrict__ bupd,
                                float* __restrict__ out) {
    int gw = (blockIdx.x * blockDim.x + threadIdx.x) >> 5;
    int lane = threadIdx.x & 31;
    if (gw >= BB * PROW) return;
    int row = gw;

    float acc[6] = {0.f, 0.f, 0.f, 0.f, 0.f, 0.f};
    const float* ocr = g_oc + (long)row * OCW;
    for (int k = lane; k < OCW; k += 32) {
        float v = ocr[k];
#pragma unroll
        for (int j = 0; j < 6; j++) acc[j] += v * g_wfold[j * OCW + k];
    }
#pragma unroll
    for (int off = 16; off > 0; off >>= 1)
#pragma unroll
        for (int j = 0; j < 6; j++)
            acc[j] += __shfl_down_sync(0xffffffffu, acc[j], off);
    if (lane != 0) return;

    float u[6];
#pragma unroll
    for (int j = 0; j < 6; j++) u[j] = acc[j] + bupd[j];

    float bq = u[0], cq = u[1], dq = u[2];
    float ninv = rsqrtf(1.f + bq * bq + cq * cq + dq * dq);
    float w = ninv, x = bq * ninv, y = cq * ninv, z = dq * ninv;
    float Ru[9];
    Ru[0] = 1.f - 2.f * (y * y + z * z); Ru[1] = 2.f * (x * y - w * z); Ru[2] = 2.f * (x * z + w * y);
    Ru[3] = 2.f * (x * y + w * z); Ru[4] = 1.f - 2.f * (x * x + z * z); Ru[5] = 2.f * (y * z - w * x);
    Ru[6] = 2.f * (x * z - w * y); Ru[7] = 2.f * (y * z + w * x); Ru[8] = 1.f - 2.f * (x * x + y * y);

    float R[9];
#pragma unroll
    for (int r = 0; r < 9; r++) R[r] = g_rP[row * 9 + r];

    float Rn[9];
#pragma unroll
    for (int r = 0; r < 3; r++)
#pragma unroll
        for (int c = 0; c < 3; c++) {
            float a = 0.f;
#pragma unroll
            for (int k = 0; k < 3; k++) a += R[r * 3 + k] * Ru[k * 3 + c];
            Rn[r * 3 + c] = a;
        }

    out[row * 3 + 0] = R[0] * u[3] + R[1] * u[4] + R[2] * u[5] + g_tP[row * 3 + 0];
    out[row * 3 + 1] = R[3] * u[3] + R[4] * u[4] + R[5] * u[5] + g_tP[row * 3 + 1];
    out[row * 3 + 2] = R[6] * u[3] + R[7] * u[4] + R[8] * u[5] + g_tP[row * 3 + 2];
    float* rout = out + BB * PROW * 3;
#pragma unroll
    for (int r = 0; r < 9; r++) rout[row * 9 + r] = Rn[r];
}

// ---------------------------------------------------------------------------
extern "C" void kernel_launch(void* const* d_in, const int* in_sizes, int n_in,
                              void* d_out, int out_size) {
    const float* trans = (const float*)d_in[0];
    const float* rots  = (const float*)d_in[1];
    const float* s     = (const float*)d_in[2];
    const float* wq    = (const float*)d_in[3];
    const float* wk    = (const float*)d_in[4];
    const float* wv    = (const float*)d_in[5];
    const float* wqp   = (const float*)d_in[6];
    const float* wkp   = (const float*)d_in[7];
    const float* wvp   = (const float*)d_in[8];
    const float* gamma = (const float*)d_in[9];
    const float* wout  = (const float*)d_in[10];
    const float* wupd  = (const float*)d_in[11];
    const float* bupd  = (const float*)d_in[12];
    float* out = (float*)d_out;

    float *p_s_pool, *p_k0, *p_v0, *p_kp0, *p_vp0, *p_q, *p_qp;
    cudaGetSymbolAddress((void**)&p_s_pool, g_s_pool);
    cudaGetSymbolAddress((void**)&p_k0, g_k0);
    cudaGetSymbolAddress((void**)&p_v0, g_v0);
    cudaGetSymbolAddress((void**)&p_kp0, g_kp0);
    cudaGetSymbolAddress((void**)&p_vp0, g_vp0);
    cudaGetSymbolAddress((void**)&p_q, g_q);
    cudaGetSymbolAddress((void**)&p_qp, g_qp);

    // 1. prep (pooled s + pooled t/r only)
    prep_all_kernel<<<(SP_TOT + TRP_TOT + 255) / 256, 256>>>(s, trans, rots);

    // 2. projection GEMMs (tf32 tensor cores)
    TaskPack P;
    int Mraw = BB * NN;
    int Mpool = BB * PROW;
    auto setTask = [&](int ti, const float* A, const float* B, float* C,
                       int M, int N, int K) {
        P.t[ti].A = A; P.t[ti].B = B; P.t[ti].C = C;
        P.t[ti].M = M; P.t[ti].N = N; P.t[ti].K = K;
        P.t[ti].gx = (N + GBN - 1) / GBN;
    };
    setTask(0, s, wk,  p_k0,  Mraw, HC,   CSD);
    setTask(1, s, wv,  p_v0,  Mraw, HC,   CSD);
    setTask(2, s, wkp, p_kp0, Mraw, HPQ3, CSD);
    setTask(3, s, wvp, p_vp0, Mraw, HPV3, CSD);
    setTask(4, p_s_pool, wq,  p_q,  Mpool, HC,   CSD);
    setTask(5, p_s_pool, wqp, p_qp, Mpool, HPQ3, CSD);
    P.ofs[0] = 0;
    for (int ti = 0; ti < NTASK; ti++) {
        int gy = (P.t[ti].M + GBM - 1) / GBM;
        P.ofs[ti + 1] = P.ofs[ti] + P.t[ti].gx * gy;
    }
    mgemm_kernel<<<P.ofs[NTASK], 256>>>(P);

    // 3. weight fold
    fold_w_kernel<<<(OCW * 32 + 255) / 256, 256>>>(wout, wupd);

    // 4. transforms
    transform_kernel<<<(XF_TOT + 255) / 256, 256>>>(trans, rots);

    // 5. split-KV attention
    attn_split_kernel<<<dim3(BB * HH, PROW / ATH, ATTS), ATH>>>(gamma);

    // 6. combine + build oc
    combine_oc_kernel<<<(BB * PROW * HH + 255) / 256, 256>>>();

    // 7. finalize
    finalize_kernel<<<(BB * PROW * 32 + 255) / 256, 256>>>(bupd, out);
}

// round 11
// speedup vs baseline: 1.4805x; 1.0514x over previous
#include <cuda_runtime.h>
#include <math.h>

// Problem constants
#define BB 2
#define NN 1024
#define CSD 384
#define HH 12
#define CC 16
#define PQN 4
#define PVN 8
#define NPAD 1026        // N + 2*PAD
#define PROW 512         // num_pool
#define TT 1538          // NPAD + PROW
#define HC 192           // H*C
#define HPQ3 144         // H*PQ*3
#define HPV3 288         // H*PV*3
#define OCW 576          // HC + HPV3 + H*PV
#define ATTS 4           // split-KV factor (proven)
#define ACHUNK ((TT + ATTS - 1) / ATTS)   // 385
#define KED 32           // extended key dim (16 + 12 + 1 + pad)

#define C1 0.176776695f       // w_l * (1/sqrt(C))
#define WC_HALF 0.117851130f  // w_c/2

typedef unsigned long long u64;

// packed f32x2 helpers (Blackwell sm_100a+)
__device__ __forceinline__ void fma2(u64 &d, u64 a, u64 b) {
    asm("fma.rn.f32x2 %0, %1, %2, %0;" : "+l"(d) : "l"(a), "l"(b));
}
__device__ __forceinline__ void mul2ip(u64 &d, u64 a) {
    asm("mul.rn.f32x2 %0, %0, %1;" : "+l"(d) : "l"(a));
}
__device__ __forceinline__ u64 pack2(float lo, float hi) {
    u64 r; asm("mov.b64 %0, {%1, %2};" : "=l"(r) : "f"(lo), "f"(hi)); return r;
}
__device__ __forceinline__ void unpack2(u64 v, float &lo, float &hi) {
    asm("mov.b64 {%0, %1}, %2;" : "=f"(lo), "=f"(hi) : "l"(v));
}
__device__ __forceinline__ unsigned f2tf32(float v) {
    unsigned r; asm("cvt.rna.tf32.f32 %0, %1;" : "=r"(r) : "f"(v)); return r;
}

// Scratch (device globals)
__device__ float g_s_pool[BB*PROW*CSD];
__device__ float g_tP[BB*PROW*3];
__device__ float g_rP[BB*PROW*9];
__device__ float g_k0 [BB*NN*HC];
__device__ float g_v0 [BB*NN*HC];
__device__ float g_kp0[BB*NN*HPQ3];
__device__ float g_vp0[BB*NN*HPV3];
__device__ float g_kpT[BB*NN*HPQ3];
__device__ float g_vpT[BB*NN*HPV3];
__device__ float g_skR[BB*NN*HH];
__device__ float g_kP [BB*PROW*HC];
__device__ float g_vP [BB*PROW*HC];
__device__ float g_kpP[BB*PROW*HPQ3];
__device__ float g_vpP[BB*PROW*HPV3];
__device__ float g_skP[BB*PROW*HH];
__device__ float g_q  [BB*PROW*HC];
__device__ float g_qp [BB*PROW*HPQ3];
__device__ float g_wfold[6*OCW];

#define NPART (BB*PROW*HH*ATTS)
__device__ float g_pm[NPART];
__device__ float g_pl[NPART];
__device__ float g_po[NPART*CC];
__device__ float g_pg[NPART*PVN*3];

__device__ __forceinline__ int clampsrc(int e) {
    int v = e - 1;
    return v < 0 ? 0 : (v > NN - 1 ? NN - 1 : v);
}

// ---------------------------------------------------------------------------
// Prep + weight fold fused (fold range is 32-aligned so warp shuffles work)
// ---------------------------------------------------------------------------
#define SP_TOT (BB*PROW*CSD)      // 393216 (mult of 32)
#define TRP_TOT (BB*PROW*12)      // 12288  (mult of 32)
#define FOLD_TOT (OCW*32)         // 18432
__global__ void prep_fold_kernel(const float* __restrict__ s,
                                 const float* __restrict__ trans,
                                 const float* __restrict__ rots,
                                 const float* __restrict__ wout,
                                 const float* __restrict__ wupd) {
    int idx = blockIdx.x * blockDim.x + threadIdx.x;
    if (idx < SP_TOT) {
        int c = idx % CSD;
        int bp = idx / CSD;
        int p = bp % PROW;
        int b = bp / PROW;
        g_s_pool[idx] = (s[(b * NN + clampsrc(2 * p    )) * CSD + c]
                       + s[(b * NN + clampsrc(2 * p + 1)) * CSD + c]
                       + s[(b * NN + clampsrc(2 * p + 2)) * CSD + c]) * (1.f / 3.f);
        return;
    }
    int k = idx - SP_TOT;
    if (k < TRP_TOT) {
        int d = k % 12;
        int bp = k / 12;
        int p = bp % PROW;
        int b = bp / PROW;
        int r0 = clampsrc(2 * p), r1 = clampsrc(2 * p + 1), r2 = clampsrc(2 * p + 2);
        if (d < 3) {
            g_tP[bp * 3 + d] = (trans[(b * NN + r0) * 3 + d]
                              + trans[(b * NN + r1) * 3 + d]
                              + trans[(b * NN + r2) * 3 + d]) * (1.f / 3.f);
        } else {
            int r = d - 3;
            g_rP[bp * 9 + r] = (rots[(b * NN + r0) * 9 + r]
                              + rots[(b * NN + r1) * 9 + r]
                              + rots[(b * NN + r2) * 9 + r]) * (1.f / 3.f);
        }
        return;
    }
    int fi = k - TRP_TOT;
    if (fi >= FOLD_TOT) return;
    int gw = fi >> 5;
    int lane = fi & 31;
    const float* wr = wout + (long)gw * CSD;
    float acc[6] = {0, 0, 0, 0, 0, 0};
    for (int m = lane; m < CSD; m += 32) {
        float w = wr[m];
#pragma unroll
        for (int j = 0; j < 6; j++) acc[j] += w * __ldg(&wupd[m * 6 + j]);
    }
#pragma unroll
    for (int off = 16; off > 0; off >>= 1)
#pragma unroll
        for (int j = 0; j < 6; j++)
            acc[j] += __shfl_down_sync(0xffffffffu, acc[j], off);
    if (lane == 0) {
#pragma unroll
        for (int j = 0; j < 6; j++) g_wfold[j * OCW + gw] = acc[j];
    }
}

// ---------------------------------------------------------------------------
// Fused multi-task GEMM on tensor cores (tf32 mma m16n8k8) — round-10 proven.
// ---------------------------------------------------------------------------
#define NTASK 6
struct GemmTask {
    const float* A;
    const float* B;
    float* C;
    int M, N, K, gx;
};
struct TaskPack {
    GemmTask t[NTASK];
    int ofs[NTASK + 1];
};

#define GBM 64
#define GBN 64
#define GBK 16
__global__ void mgemm_kernel(TaskPack P) {
    int bid = blockIdx.x;
    int ti = 0;
#pragma unroll
    for (int x = 0; x < NTASK - 1; x++)
        if (bid >= P.ofs[x + 1]) ti = x + 1;
    GemmTask tk = P.t[ti];
    int lb = bid - P.ofs[ti];
    int bx = lb % tk.gx, by = lb / tk.gx;

    __shared__ unsigned As[GBM][GBK + 1];
    __shared__ unsigned Bs[GBK][GBN + 8];

    int tid = threadIdx.x;
    int warp = tid >> 5, lane = tid & 31;
    int gid = lane >> 2, tig = lane & 3;
    int wm = warp & 3;
    int wn = warp >> 2;
    int row0 = by * GBM;
    int col0 = bx * GBN;
    const float* A = tk.A;
    const float* Bm = tk.B;
    int M = tk.M, Nn = tk.N, K = tk.K;

    float d[4][4];
#pragma unroll
    for (int t = 0; t < 4; t++)
#pragma unroll
        for (int c = 0; c < 4; c++) d[t][c] = 0.f;

    for (int k0 = 0; k0 < K; k0 += GBK) {
#pragma unroll
        for (int x = 0; x < 4; x++) {
            int li = tid + x * 256;
            int m = li >> 4, kk = li & 15;
            int gm = row0 + m;
            float v = (gm < M) ? A[(long)gm * K + k0 + kk] : 0.f;
            As[m][kk] = f2tf32(v);
        }
#pragma unroll
        for (int x = 0; x < 4; x++) {
            int li = tid + x * 256;
            int kk = li >> 6, n = li & 63;
            int gn = col0 + n;
            float v = (gn < Nn) ? Bm[(long)(k0 + kk) * Nn + gn] : 0.f;
            Bs[kk][n] = f2tf32(v);
        }
        __syncthreads();

#pragma unroll
        for (int ks = 0; ks < 2; ks++) {
            int kb = ks * 8;
            int ra = wm * 16 + gid;
            unsigned a0 = As[ra][kb + tig];
            unsigned a1 = As[ra + 8][kb + tig];
            unsigned a2 = As[ra][kb + tig + 4];
            unsigned a3 = As[ra + 8][kb + tig + 4];
#pragma unroll
            for (int t = 0; t < 4; t++) {
                int nb = wn * 32 + t * 8;
                unsigned b0 = Bs[kb + tig][nb + gid];
                unsigned b1 = Bs[kb + tig + 4][nb + gid];
                asm volatile(
                    "mma.sync.aligned.m16n8k8.row.col.f32.tf32.tf32.f32 "
                    "{%0,%1,%2,%3}, {%4,%5,%6,%7}, {%8,%9}, {%0,%1,%2,%3};"
                    : "+f"(d[t][0]), "+f"(d[t][1]), "+f"(d[t][2]), "+f"(d[t][3])
                    : "r"(a0), "r"(a1), "r"(a2), "r"(a3), "r"(b0), "r"(b1));
            }
        }
        __syncthreads();
    }

#pragma unroll
    for (int t = 0; t < 4; t++) {
        int gn0 = col0 + wn * 32 + t * 8 + tig * 2;
        int gm0 = row0 + wm * 16 + gid;
        if (gm0 < M) {
            if (gn0 < Nn)     tk.C[(long)gm0 * Nn + gn0]     = d[t][0];
            if (gn0 + 1 < Nn) tk.C[(long)gm0 * Nn + gn0 + 1] = d[t][1];
        }
        int gm1 = gm0 + 8;
        if (gm1 < M) {
            if (gn0 < Nn)     tk.C[(long)gm1 * Nn + gn0]     = d[t][2];
            if (gn0 + 1 < Nn) tk.C[(long)gm1 * Nn + gn0 + 1] = d[t][3];
        }
    }
}

// ---------------------------------------------------------------------------
// Transform kernel (round-9 proven), 4 ranges.
// ---------------------------------------------------------------------------
#define RAWPT (BB*NN*HH)
#define POOLKV (BB*PROW*(HC/4)*2)
#define POOLPT (BB*PROW*HH)
#define QPT (BB*PROW*HH)
#define XF_TOT (RAWPT + POOLKV + POOLPT + QPT)

__device__ __forceinline__ float4 avg3f4(float4 a, float4 b, float4 c) {
    return make_float4((a.x + b.x + c.x) * (1.f / 3.f),
                       (a.y + b.y + c.y) * (1.f / 3.f),
                       (a.z + b.z + c.z) * (1.f / 3.f),
                       (a.w + b.w + c.w) * (1.f / 3.f));
}

__global__ void transform_kernel(const float* __restrict__ trans,
                                 const float* __restrict__ rots) {
    int idx = blockIdx.x * blockDim.x + threadIdx.x;
    if (idx < RAWPT) {
        int h = idx % HH;
        int rn = idx / HH;
        float R[9], tr[3];
#pragma unroll
        for (int r = 0; r < 9; r++) R[r] = rots[rn * 9 + r];
#pragma unroll
        for (int r = 0; r < 3; r++) tr[r] = trans[rn * 3 + r];

        {
            const float4* src = reinterpret_cast<const float4*>(g_kp0 + ((long)rn * HPQ3 + h * PQN * 3));
            float lp[PQN * 3];
#pragma unroll
            for (int c = 0; c < 3; c++) {
                float4 v = src[c];
                lp[c*4+0] = v.x; lp[c*4+1] = v.y; lp[c*4+2] = v.z; lp[c*4+3] = v.w;
            }
            float sk = 0.f;
            float gp[PQN * 3];
#pragma unroll
            for (int p = 0; p < PQN; p++) {
                float lx = lp[p*3+0], ly = lp[p*3+1], lz = lp[p*3+2];
                float gx = R[0]*lx + R[1]*ly + R[2]*lz + tr[0];
                float gy = R[3]*lx + R[4]*ly + R[5]*lz + tr[1];
                float gz = R[6]*lx + R[7]*ly + R[8]*lz + tr[2];
                gp[p*3+0] = gx; gp[p*3+1] = gy; gp[p*3+2] = gz;
                sk += gx*gx + gy*gy + gz*gz;
            }
            g_skR[rn * HH + h] = sk;
            float4* dst = reinterpret_cast<float4*>(g_kpT + ((long)rn * HPQ3 + h * PQN * 3));
#pragma unroll
            for (int c = 0; c < 3; c++)
                dst[c] = make_float4(gp[c*4+0], gp[c*4+1], gp[c*4+2], gp[c*4+3]);
        }
        {
            const float4* src = reinterpret_cast<const float4*>(g_vp0 + ((long)rn * HPV3 + h * PVN * 3));
            float lp[PVN * 3];
#pragma unroll
            for (int c = 0; c < 6; c++) {
                float4 v = src[c];
                lp[c*4+0] = v.x; lp[c*4+1] = v.y; lp[c*4+2] = v.z; lp[c*4+3] = v.w;
            }
            float gp[PVN * 3];
#pragma unroll
            for (int p = 0; p < PVN; p++) {
                float lx = lp[p*3+0], ly = lp[p*3+1], lz = lp[p*3+2];
                gp[p*3+0] = R[0]*lx + R[1]*ly + R[2]*lz + tr[0];
                gp[p*3+1] = R[3]*lx + R[4]*ly + R[5]*lz + tr[1];
                gp[p*3+2] = R[6]*lx + R[7]*ly + R[8]*lz + tr[2];
            }
            float4* dst = reinterpret_cast<float4*>(g_vpT + ((long)rn * HPV3 + h * PVN * 3));
#pragma unroll
            for (int c = 0; c < 6; c++)
                dst[c] = make_float4(gp[c*4+0], gp[c*4+1], gp[c*4+2], gp[c*4+3]);
        }
        return;
    }
    int i2 = idx - RAWPT;
    if (i2 < POOLKV) {
        int c = i2 % (HC / 4);
        int rest = i2 / (HC / 4);
        int rp = rest % (BB * PROW);
        int sel = rest / (BB * PROW);
        int p = rp % PROW;
        int b = rp / PROW;
        int r0 = clampsrc(2 * p), r1 = clampsrc(2 * p + 1), r2 = clampsrc(2 * p + 2);
        const float* srcbase = sel ? g_v0 : g_k0;
        float* dstbase = sel ? g_vP : g_kP;
        float4 a = reinterpret_cast<const float4*>(srcbase + ((long)(b * NN + r0) * HC))[c];
        float4 bb = reinterpret_cast<const float4*>(srcbase + ((long)(b * NN + r1) * HC))[c];
        float4 cc = reinterpret_cast<const float4*>(srcbase + ((long)(b * NN + r2) * HC))[c];
        reinterpret_cast<float4*>(dstbase + ((long)rp * HC))[c] = avg3f4(a, bb, cc);
        return;
    }
    int i3 = i2 - POOLKV;
    if (i3 < POOLPT) {
        int h = i3 % HH;
        int rp = i3 / HH;
        int p = rp % PROW;
        int b = rp / PROW;
        int r0 = clampsrc(2 * p), r1 = clampsrc(2 * p + 1), r2 = clampsrc(2 * p + 2);
        float R[9], tr[3];
#pragma unroll
        for (int r = 0; r < 9; r++) R[r] = g_rP[rp * 9 + r];
#pragma unroll
        for (int r = 0; r < 3; r++) tr[r] = g_tP[rp * 3 + r];

        {
            float lp[PQN * 3];
            const float4* a = reinterpret_cast<const float4*>(g_kp0 + ((long)(b * NN + r0) * HPQ3 + h * PQN * 3));
            const float4* bb = reinterpret_cast<const float4*>(g_kp0 + ((long)(b * NN + r1) * HPQ3 + h * PQN * 3));
            const float4* cc = reinterpret_cast<const float4*>(g_kp0 + ((long)(b * NN + r2) * HPQ3 + h * PQN * 3));
#pragma unroll
            for (int c = 0; c < 3; c++) {
                float4 v = avg3f4(a[c], bb[c], cc[c]);
                lp[c*4+0] = v.x; lp[c*4+1] = v.y; lp[c*4+2] = v.z; lp[c*4+3] = v.w;
            }
            float sk = 0.f;
            float gp[PQN * 3];
#pragma unroll
            for (int pp = 0; pp < PQN; pp++) {
                float lx = lp[pp*3+0], ly = lp[pp*3+1], lz = lp[pp*3+2];
                float gx = R[0]*lx + R[1]*ly + R[2]*lz + tr[0];
                float gy = R[3]*lx + R[4]*ly + R[5]*lz + tr[1];
                float gz = R[6]*lx + R[7]*ly + R[8]*lz + tr[2];
                gp[pp*3+0] = gx; gp[pp*3+1] = gy; gp[pp*3+2] = gz;
                sk += gx*gx + gy*gy + gz*gz;
            }
            g_skP[rp * HH + h] = sk;
            float4* dst = reinterpret_cast<float4*>(g_kpP + ((long)rp * HPQ3 + h * PQN * 3));
#pragma unroll
            for (int c = 0; c < 3; c++)
                dst[c] = make_float4(gp[c*4+0], gp[c*4+1], gp[c*4+2], gp[c*4+3]);
        }
        {
            float lp[PVN * 3];
            const float4* a = reinterpret_cast<const float4*>(g_vp0 + ((long)(b * NN + r0) * HPV3 + h * PVN * 3));
            const float4* bb = reinterpret_cast<const float4*>(g_vp0 + ((long)(b * NN + r1) * HPV3 + h * PVN * 3));
            const float4* cc = reinterpret_cast<const float4*>(g_vp0 + ((long)(b * NN + r2) * HPV3 + h * PVN * 3));
#pragma unroll
            for (int c = 0; c < 6; c++) {
                float4 v = avg3f4(a[c], bb[c], cc[c]);
                lp[c*4+0] = v.x; lp[c*4+1] = v.y; lp[c*4+2] = v.z; lp[c*4+3] = v.w;
            }
            float gp[PVN * 3];
#pragma unroll
            for (int pp = 0; pp < PVN; pp++) {
                float lx = lp[pp*3+0], ly = lp[pp*3+1], lz = lp[pp*3+2];
                gp[pp*3+0] = R[0]*lx + R[1]*ly + R[2]*lz + tr[0];
                gp[pp*3+1] = R[3]*lx + R[4]*ly + R[5]*lz + tr[1];
                gp[pp*3+2] = R[6]*lx + R[7]*ly + R[8]*lz + tr[2];
            }
            float4* dst = reinterpret_cast<float4*>(g_vpP + ((long)rp * HPV3 + h * PVN * 3));
#pragma unroll
            for (int c = 0; c < 6; c++)
                dst[c] = make_float4(gp[c*4+0], gp[c*4+1], gp[c*4+2], gp[c*4+3]);
        }
        return;
    }
    int i4 = i3 - POOLPT;
    if (i4 >= QPT) return;
    int h = i4 % HH;
    int rp = i4 / HH;
    float R[9], tr[3];
#pragma unroll
    for (int r = 0; r < 9; r++) R[r] = g_rP[rp * 9 + r];
#pragma unroll
    for (int r = 0; r < 3; r++) tr[r] = g_tP[rp * 3 + r];
    float lp[PQN * 3];
    float4* qp4 = reinterpret_cast<float4*>(g_qp + ((long)rp * HPQ3 + h * PQN * 3));
#pragma unroll
    for (int c = 0; c < 3; c++) {
        float4 v = qp4[c];
        lp[c*4+0] = v.x; lp[c*4+1] = v.y; lp[c*4+2] = v.z; lp[c*4+3] = v.w;
    }
    float gp[PQN * 3];
#pragma unroll
    for (int p = 0; p < PQN; p++) {
        float lx = lp[p*3+0], ly = lp[p*3+1], lz = lp[p*3+2];
        gp[p*3+0] = R[0]*lx + R[1]*ly + R[2]*lz + tr[0];
        gp[p*3+1] = R[3]*lx + R[4]*ly + R[5]*lz + tr[1];
        gp[p*3+2] = R[6]*lx + R[7]*ly + R[8]*lz + tr[2];
    }
#pragma unroll
    for (int c = 0; c < 3; c++)
        qp4[c] = make_float4(gp[c*4+0], gp[c*4+1], gp[c*4+2], gp[c*4+3]);
}

// ---------------------------------------------------------------------------
// Split-KV attention with extended-key fused logit:
//   lg (+ const) = qe . ke,  qe=[C1*q, 2g*qg, -g, 0..], ke=[k, kg, sk, 0..]
// The dropped -g*sq term is a per-query constant -> softmax invariant.
// ---------------------------------------------------------------------------
#define TJ 32
#define ATH 64
__global__ void attn_split_kernel(const float* __restrict__ gamma) {
    int bh = blockIdx.x;
    int b = bh / HH, h = bh % HH;
    int i = blockIdx.y * ATH + threadIdx.x;
    int sp = blockIdx.z;
    int tid = threadIdx.x;

    int j_begin = sp * ACHUNK;
    int j_end = j_begin + ACHUNK;
    if (j_end > TT) j_end = TT;

    __shared__ __align__(16) float ke_s[TJ][KED];
    __shared__ __align__(16) float v_s [TJ][CC];
    __shared__ __align__(16) float vg_s[TJ][PVN * 3];

    float gm = gamma[h];
    float gcoef = logf(1.f + __expf(gm)) * WC_HALF;

    int qrow = b * PROW + i;
    u64 qe2[KED / 2];
    {
        const u64* q64 = reinterpret_cast<const u64*>(g_q + (long)qrow * HC + h * CC);
        u64 c1p = pack2(C1, C1);
#pragma unroll
        for (int c = 0; c < CC / 2; c++) { qe2[c] = q64[c]; mul2ip(qe2[c], c1p); }
        const u64* g64 = reinterpret_cast<const u64*>(g_qp + (long)qrow * HPQ3 + h * PQN * 3);
        u64 g2p = pack2(2.f * gcoef, 2.f * gcoef);
#pragma unroll
        for (int c = 0; c < PQN * 3 / 2; c++) { qe2[8 + c] = g64[c]; mul2ip(qe2[8 + c], g2p); }
        qe2[14] = pack2(-gcoef, 0.f);
        qe2[15] = 0ULL;
    }

    float mrun = -1e30f, lrun = 0.f;
    u64 ao2[CC / 2], ag2[PVN * 3 / 2];
#pragma unroll
    for (int c = 0; c < CC / 2; c++) ao2[c] = 0ULL;
#pragma unroll
    for (int x = 0; x < PVN * 3 / 2; x++) ag2[x] = 0ULL;

    for (int j0 = j_begin; j0 < j_end; j0 += TJ) {
        __syncthreads();
        // ke: 8 float4 chunks per key: [0..3]=k, [4..6]=kg, [7]=(sk,0,0,0)
        for (int x = tid; x < TJ * 8; x += ATH) {
            int j = x >> 3, c4 = x & 7;
            int jj = j0 + j;
            float4 v = make_float4(0.f, 0.f, 0.f, 0.f);
            if (jj < TT) {
                bool raw = (jj < NPAD);
                long rr = raw ? (long)(b * NN + clampsrc(jj)) : (long)(b * PROW + (jj - NPAD));
                if (c4 < 4) {
                    const float* base = raw ? g_k0 : g_kP;
                    v = reinterpret_cast<const float4*>(base + rr * HC + h * CC)[c4];
                } else if (c4 < 7) {
                    const float* base = raw ? g_kpT : g_kpP;
                    v = reinterpret_cast<const float4*>(base + rr * HPQ3 + h * PQN * 3)[c4 - 4];
                } else {
                    const float* base = raw ? g_skR : g_skP;
                    v.x = base[rr * HH + h];
                }
            }
            reinterpret_cast<float4*>(&ke_s[j][0])[c4] = v;
        }
        for (int x = tid; x < TJ * 4; x += ATH) {
            int j = x >> 2, c4 = x & 3;
            int jj = j0 + j;
            float4 v = make_float4(0.f, 0.f, 0.f, 0.f);
            if (jj < TT) {
                bool raw = (jj < NPAD);
                long rr = raw ? (long)(b * NN + clampsrc(jj)) : (long)(b * PROW + (jj - NPAD));
                const float* base = raw ? g_v0 : g_vP;
                v = reinterpret_cast<const float4*>(base + rr * HC + h * CC)[c4];
            }
            reinterpret_cast<float4*>(&v_s[j][0])[c4] = v;
        }
        for (int x = tid; x < TJ * 6; x += ATH) {
            int j = x / 6, c4 = x % 6;
            int jj = j0 + j;
            float4 v = make_float4(0.f, 0.f, 0.f, 0.f);
            if (jj < TT) {
                bool raw = (jj < NPAD);
                long rr = raw ? (long)(b * NN + clampsrc(jj)) : (long)(b * PROW + (jj - NPAD));
                const float* base = raw ? g_vpT : g_vpP;
                v = reinterpret_cast<const float4*>(base + rr * HPV3 + h * PVN * 3)[c4];
            }
            reinterpret_cast<float4*>(&vg_s[j][0])[c4] = v;
        }
        __syncthreads();

        int nv = j_end - j0;
        if (nv > TJ) nv = TJ;

        float logit[TJ];
        float tmax = -1e30f;
#pragma unroll
        for (int jj = 0; jj < TJ; jj++) {
            u64 a1 = 0ULL;
            const ulonglong2* ke128 = reinterpret_cast<const ulonglong2*>(&ke_s[jj][0]);
#pragma unroll
            for (int c = 0; c < KED / 4; c++) {
                ulonglong2 kv = ke128[c];
                fma2(a1, qe2[2*c], kv.x);
                fma2(a1, qe2[2*c+1], kv.y);
            }
            float l1, h1;
            unpack2(a1, l1, h1);
            float lg = l1 + h1;
            logit[jj] = (jj < nv) ? lg : -1e30f;
            tmax = fmaxf(tmax, logit[jj]);
        }
        float mn = fmaxf(mrun, tmax);
        float corr = __expf(mrun - mn);
        lrun *= corr;
        u64 corr2 = pack2(corr, corr);
#pragma unroll
        for (int c = 0; c < CC / 2; c++) mul2ip(ao2[c], corr2);
#pragma unroll
        for (int x = 0; x < PVN * 3 / 2; x++) mul2ip(ag2[x], corr2);
#pragma unroll
        for (int jj = 0; jj < TJ; jj++) {
            float e = __expf(logit[jj] - mn);
            lrun += e;
            u64 ee = pack2(e, e);
            const ulonglong2* v128 = reinterpret_cast<const ulonglong2*>(&v_s[jj][0]);
#pragma unroll
            for (int c = 0; c < CC / 4; c++) {
                ulonglong2 vv = v128[c];
                fma2(ao2[2*c], ee, vv.x);
                fma2(ao2[2*c+1], ee, vv.y);
            }
            const ulonglong2* g128 = reinterpret_cast<const ulonglong2*>(&vg_s[jj][0]);
#pragma unroll
            for (int c = 0; c < PVN * 3 / 4; c++) {
                ulonglong2 vv = g128[c];
                fma2(ag2[2*c], ee, vv.x);
                fma2(ag2[2*c+1], ee, vv.y);
            }
        }
        mrun = mn;
    }

    int p = (qrow * HH + h) * ATTS + sp;
    g_pm[p] = mrun;
    g_pl[p] = lrun;
#pragma unroll
    for (int c = 0; c < CC / 2; c++) {
        float lo, hi; unpack2(ao2[c], lo, hi);
        g_po[(long)p * CC + 2*c] = lo;
        g_po[(long)p * CC + 2*c + 1] = hi;
    }
#pragma unroll
    for (int x = 0; x < PVN * 3 / 2; x++) {
        float lo, hi; unpack2(ag2[x], lo, hi);
        g_pg[(long)p * (PVN * 3) + 2*x] = lo;
        g_pg[(long)p * (PVN * 3) + 2*x + 1] = hi;
    }
}

// ---------------------------------------------------------------------------
// Combine + finalize fused: block handles 16 rows.
// Phase 1 (192 of 512 threads): combine split partials -> smem oc rows.
// Phase 2 (16 warps): wfold dot + quaternion update + output.
// ---------------------------------------------------------------------------
#define RPB 16
__global__ void combine_finalize_kernel(const float* __restrict__ bupd,
                                        float* __restrict__ out) {
    __shared__ float soc[RPB][OCW];
    int tid = threadIdx.x;
    int row0 = blockIdx.x * RPB;

    // Phase 1: combine, unit = (r, h)
    if (tid < RPB * HH) {
        int r = tid / HH;
        int h = tid % HH;
        int row = row0 + r;
        int p0 = (row * HH + h) * ATTS;

        float m = -1e30f;
#pragma unroll
        for (int s = 0; s < ATTS; s++) m = fmaxf(m, g_pm[p0 + s]);
        float L = 0.f;
        float o[CC], g[PVN * 3];
#pragma unroll
        for (int c = 0; c < CC; c++) o[c] = 0.f;
#pragma unroll
        for (int x = 0; x < PVN * 3; x++) g[x] = 0.f;
#pragma unroll
        for (int s = 0; s < ATTS; s++) {
            float w = __expf(g_pm[p0 + s] - m);
            L += g_pl[p0 + s] * w;
            const float* po = g_po + (long)(p0 + s) * CC;
            const float* pg = g_pg + (long)(p0 + s) * (PVN * 3);
#pragma unroll
            for (int c = 0; c < CC; c++) o[c] += w * po[c];
#pragma unroll
            for (int x = 0; x < PVN * 3; x++) g[x] += w * pg[x];
        }
        float inv = 1.f / L;
#pragma unroll
        for (int c = 0; c < CC; c++) o[c] *= inv;
#pragma unroll
        for (int x = 0; x < PVN * 3; x++) g[x] *= inv;

        float R[9], tr[3];
#pragma unroll
        for (int r9 = 0; r9 < 9; r9++) R[r9] = g_rP[row * 9 + r9];
#pragma unroll
        for (int r3 = 0; r3 < 3; r3++) tr[r3] = g_tP[row * 3 + r3];

#pragma unroll
        for (int c = 0; c < CC; c++) soc[r][h * CC + c] = o[c];
#pragma unroll
        for (int pp = 0; pp < PVN; pp++) {
            float gx = g[pp * 3 + 0] - tr[0];
            float gy = g[pp * 3 + 1] - tr[1];
            float gz = g[pp * 3 + 2] - tr[2];
            float lx = R[0] * gx + R[3] * gy + R[6] * gz;
            float ly = R[1] * gx + R[4] * gy + R[7] * gz;
            float lz = R[2] * gx + R[5] * gy + R[8] * gz;
            soc[r][HC + h * PVN * 3 + pp * 3 + 0] = lx;
            soc[r][HC + h * PVN * 3 + pp * 3 + 1] = ly;
            soc[r][HC + h * PVN * 3 + pp * 3 + 2] = lz;
            soc[r][HC + HPV3 + h * PVN + pp] =
                sqrtf(lx * lx + ly * ly + lz * lz + 1e-8f);
        }
    }
    __syncthreads();

    // Phase 2: one warp per row
    int warp = tid >> 5;
    int lane = tid & 31;
    int row = row0 + warp;

    float acc[6] = {0.f, 0.f, 0.f, 0.f, 0.f, 0.f};
    for (int k = lane; k < OCW; k += 32) {
        float v = soc[warp][k];
#pragma unroll
        for (int j = 0; j < 6; j++) acc[j] += v * g_wfold[j * OCW + k];
    }
#pragma unroll
    for (int off = 16; off > 0; off >>= 1)
#pragma unroll
        for (int j = 0; j < 6; j++)
            acc[j] += __shfl_down_sync(0xffffffffu, acc[j], off);
    if (lane != 0) return;

    float u[6];
#pragma unroll
    for (int j = 0; j < 6; j++) u[j] = acc[j] + bupd[j];

    float bq = u[0], cq = u[1], dq = u[2];
    float ninv = rsqrtf(1.f + bq * bq + cq * cq + dq * dq);
    float w = ninv, x = bq * ninv, y = cq * ninv, z = dq * ninv;
    float Ru[9];
    Ru[0] = 1.f - 2.f * (y * y + z * z); Ru[1] = 2.f * (x * y - w * z); Ru[2] = 2.f * (x * z + w * y);
    Ru[3] = 2.f * (x * y + w * z); Ru[4] = 1.f - 2.f * (x * x + z * z); Ru[5] = 2.f * (y * z - w * x);
    Ru[6] = 2.f * (x * z - w * y); Ru[7] = 2.f * (y * z + w * x); Ru[8] = 1.f - 2.f * (x * x + y * y);

    float R[9];
#pragma unroll
    for (int r = 0; r < 9; r++) R[r] = g_rP[row * 9 + r];

    float Rn[9];
#pragma unroll
    for (int r = 0; r < 3; r++)
#pragma unroll
        for (int c = 0; c < 3; c++) {
            float a = 0.f;
#pragma unroll
            for (int k = 0; k < 3; k++) a += R[r * 3 + k] * Ru[k * 3 + c];
            Rn[r * 3 + c] = a;
        }

    out[row * 3 + 0] = R[0] * u[3] + R[1] * u[4] + R[2] * u[5] + g_tP[row * 3 + 0];
    out[row * 3 + 1] = R[3] * u[3] + R[4] * u[4] + R[5] * u[5] + g_tP[row * 3 + 1];
    out[row * 3 + 2] = R[6] * u[3] + R[7] * u[4] + R[8] * u[5] + g_tP[row * 3 + 2];
    float* rout = out + BB * PROW * 3;
#pragma unroll
    for (int r = 0; r < 9; r++) rout[row * 9 + r] = Rn[r];
}

// ---------------------------------------------------------------------------
extern "C" void kernel_launch(void* const* d_in, const int* in_sizes, int n_in,
                              void* d_out, int out_size) {
    const float* trans = (const float*)d_in[0];
    const float* rots  = (const float*)d_in[1];
    const float* s     = (const float*)d_in[2];
    const float* wq    = (const float*)d_in[3];
    const float* wk    = (const float*)d_in[4];
    const float* wv    = (const float*)d_in[5];
    const float* wqp   = (const float*)d_in[6];
    const float* wkp   = (const float*)d_in[7];
    const float* wvp   = (const float*)d_in[8];
    const float* gamma = (const float*)d_in[9];
    const float* wout  = (const float*)d_in[10];
    const float* wupd  = (const float*)d_in[11];
    const float* bupd  = (const float*)d_in[12];
    float* out = (float*)d_out;

    float *p_s_pool, *p_k0, *p_v0, *p_kp0, *p_vp0, *p_q, *p_qp;
    cudaGetSymbolAddress((void**)&p_s_pool, g_s_pool);
    cudaGetSymbolAddress((void**)&p_k0, g_k0);
    cudaGetSymbolAddress((void**)&p_v0, g_v0);
    cudaGetSymbolAddress((void**)&p_kp0, g_kp0);
    cudaGetSymbolAddress((void**)&p_vp0, g_vp0);
    cudaGetSymbolAddress((void**)&p_q, g_q);
    cudaGetSymbolAddress((void**)&p_qp, g_qp);

    // 1. prep + weight fold (fused)
    prep_fold_kernel<<<(SP_TOT + TRP_TOT + FOLD_TOT + 255) / 256, 256>>>(
        s, trans, rots, wout, wupd);

    // 2. projection GEMMs (tf32 tensor cores)
    TaskPack P;
    int Mraw = BB * NN;
    int Mpool = BB * PROW;
    auto setTask = [&](int ti, const float* A, const float* B, float* C,
                       int M, int N, int K) {
        P.t[ti].A = A; P.t[ti].B = B; P.t[ti].C = C;
        P.t[ti].M = M; P.t[ti].N = N; P.t[ti].K = K;
        P.t[ti].gx = (N + GBN - 1) / GBN;
    };
    setTask(0, s, wk,  p_k0,  Mraw, HC,   CSD);
    setTask(1, s, wv,  p_v0,  Mraw, HC,   CSD);
    setTask(2, s, wkp, p_kp0, Mraw, HPQ3, CSD);
    setTask(3, s, wvp, p_vp0, Mraw, HPV3, CSD);
    setTask(4, p_s_pool, wq,  p_q,  Mpool, HC,   CSD);
    setTask(5, p_s_pool, wqp, p_qp, Mpool, HPQ3, CSD);
    P.ofs[0] = 0;
    for (int ti = 0; ti < NTASK; ti++) {
        int gy = (P.t[ti].M + GBM - 1) / GBM;
        P.ofs[ti + 1] = P.ofs[ti] + P.t[ti].gx * gy;
    }
    mgemm_kernel<<<P.ofs[NTASK], 256>>>(P);

    // 3. transforms
    transform_kernel<<<(XF_TOT + 255) / 256, 256>>>(trans, rots);

    // 4. split-KV attention (extended-key fused logit)
    attn_split_kernel<<<dim3(BB * HH, PROW / ATH, ATTS), ATH>>>(gamma);

    // 5. combine + finalize (fused)
    combine_finalize_kernel<<<(BB * PROW) / RPB, RPB * 32>>>(bupd, out);
}